// round 11
// baseline (speedup 1.0000x reference)
#include <cuda_runtime.h>
#include <cuda_fp16.h>
#include <math.h>
#include <stdint.h>

#define BATCH 4
#define SEQ   4096
#define DIM   1024
#define HEADS 16
#define DH    64
#define CHUNK 128
#define NCHUNK 32
#define BH    (BATCH*HEADS)
#define FEAT_SCALE 0.35355339059327373f  // 64^-0.25

// ---------------- scratch (device globals; no allocation allowed) ----------------
__device__ __half g_xh   [BATCH*SEQ*DIM];     // fp16 x
__device__ __half g_wqkvT[3*DIM*DIM];         // K-major fp16
__device__ __half g_woutT[DIM*DIM];           // K-major fp16
__device__ __half g_qh  [BH*SEQ*DH];          // featurized q (fp16)
__device__ __half g_kh  [BH*SEQ*DH];          // featurized k (fp16)
__device__ __half g_vh  [BH*SEQ*DH];          // v (fp16)
__device__ __half g_attnh[BATCH*SEQ*DIM];     // attention out, fp16
__device__ float  g_kvch[BH*NCHUNK*DH*DH];
__device__ float  g_ksch[BH*NCHUNK*DH];

// ---------------- helpers ----------------
__device__ __forceinline__ uint32_t h2_to_u32(__half2 h) {
    __half2_raw r = *(__half2_raw*)&h;
    return (uint32_t)r.x | ((uint32_t)r.y << 16);
}
__device__ __forceinline__ __half2 u32_to_h2(uint32_t u) {
    __half2_raw r;
    r.x = (unsigned short)(u & 0xFFFF);
    r.y = (unsigned short)(u >> 16);
    return *(__half2*)&r;
}
__device__ __forceinline__ void cpasync16(void* dst, const void* src) {
    unsigned d = (unsigned)__cvta_generic_to_shared(dst);
    asm volatile("cp.async.ca.shared.global [%0], [%1], 16;" :: "r"(d), "l"(src));
}
#define CP_COMMIT()  asm volatile("cp.async.commit_group;")
#define CP_WAIT1()   asm volatile("cp.async.wait_group 1;")

#define MMA_F16(acc, a0, a1, a2, a3, b0, b1) \
    asm volatile("mma.sync.aligned.m16n8k16.row.col.f32.f16.f16.f32 " \
        "{%0,%1,%2,%3}, {%4,%5,%6,%7}, {%8,%9}, {%0,%1,%2,%3};" \
        : "+f"((acc)[0]), "+f"((acc)[1]), "+f"((acc)[2]), "+f"((acc)[3]) \
        : "r"(a0), "r"(a1), "r"(a2), "r"(a3), "r"(b0), "r"(b1))

#define LDMATRIX_X4(r0, r1, r2, r3, addr) \
    asm volatile("ldmatrix.sync.aligned.m8n8.x4.shared.b16 {%0,%1,%2,%3}, [%4];" \
        : "=r"(r0), "=r"(r1), "=r"(r2), "=r"(r3) : "r"(addr))

#define LDMATRIX_X4_TRANS(r0, r1, r2, r3, addr) \
    asm volatile("ldmatrix.sync.aligned.m8n8.x4.trans.shared.b16 {%0,%1,%2,%3}, [%4];" \
        : "=r"(r0), "=r"(r1), "=r"(r2), "=r"(r3) : "r"(addr))

__device__ __forceinline__ uint32_t smem_u32p(const void* p) {
    return (uint32_t)__cvta_generic_to_shared(p);
}

// fp32 sincos, FMA Cody-Waite range reduction (accurate ~1e-7 for ang < 5000)
__device__ __forceinline__ void rope_sincos_f(float ang, float& s, float& c) {
    float qf = rintf(ang * 0.63661977f);
    float r = fmaf(-qf, 1.57079637e+0f, ang);
    r = fmaf(qf, 4.37113900e-8f, r);
    int qi = (int)qf & 3;
    float r2 = r * r;
    float sp = r * (1.0f + r2 * (-1.6666667e-1f + r2 * (8.3333337e-3f
              + r2 * (-1.9841270e-4f + r2 * 2.7557319e-6f))));
    float cp = 1.0f + r2 * (-0.5f + r2 * (4.1666668e-2f
              + r2 * (-1.3888889e-3f + r2 * 2.4801587e-5f)));
    switch (qi) {
        case 0:  s =  sp; c =  cp; break;
        case 1:  s =  cp; c = -sp; break;
        case 2:  s = -sp; c = -cp; break;
        default: s = -cp; c =  sp; break;
    }
}

// ---------------- fp16 conversion pre-passes ----------------
__global__ void f32_to_f16_kernel(const float2* __restrict__ in, __half2* __restrict__ out, int n2) {
    int i = blockIdx.x * blockDim.x + threadIdx.x;
    if (i < n2) out[i] = __float22half2_rn(in[i]);
}

__global__ void transpose_f16(const float* __restrict__ W, __half* __restrict__ WT,
                              int K, int Nn) {
    __shared__ float t[32][33];
    int n0 = blockIdx.x * 32, k0 = blockIdx.y * 32;
    int tx = threadIdx.x, ty = threadIdx.y;
#pragma unroll
    for (int i = 0; i < 32; i += 8)
        t[ty + i][tx] = W[(size_t)(k0 + ty + i) * Nn + n0 + tx];
    __syncthreads();
#pragma unroll
    for (int i = 0; i < 32; i += 8)
        WT[(size_t)(n0 + ty + i) * K + k0 + tx] = __float2half(t[tx][ty + i]);
}

// ================== shared GEMM mainloop (CTA 128x256, warp 64x64) ==================
// A: [M][K] fp16 row-major; BT: [Nn][K] fp16 K-major. 256 threads, 8 warps 2x4.
// Stage: A 128x32 (pitch 80B) + B 256x32 (pitch 80B) = 30720 B; 3 stages.
#define STAGE_B 30720

#define GEMM_MAINLOOP(ACC, A_PTR, BT_PTR, KDIM)                                        \
    const int tid = threadIdx.x;                                                       \
    const int warp = tid >> 5, lane = tid & 31;                                        \
    const int gid = lane >> 2, tig = lane & 3;                                         \
    const int g = lane >> 3, rr = lane & 7;                                            \
    const int warpM = warp & 1, warpN = warp >> 1;                                     \
    const int mBase = warpM * 64;                                                      \
    const int nBase = warpN * 64;                                                      \
    const uint32_t smbase = smem_u32p(smc);                                            \
    const int KT = (KDIM) >> 5;                                                        \
    auto load_tile = [&](int kt, char* buf) {                                          \
        char* As = buf;                                                                \
        char* Bs = buf + 10240;                                                        \
        int k0 = kt * 32;                                                              \
        _Pragma("unroll")                                                              \
        for (int i = 0; i < 2; i++) {                                                  \
            int c = i * 256 + tid;                                                     \
            int m = c >> 2, k8 = (c & 3) * 8;                                          \
            cpasync16(As + m * 80 + k8 * 2, (A_PTR) + (size_t)m * (KDIM) + k0 + k8);   \
        }                                                                              \
        _Pragma("unroll")                                                              \
        for (int i = 0; i < 4; i++) {                                                  \
            int c = i * 256 + tid;                                                     \
            int n = c >> 2, k8 = (c & 3) * 8;                                          \
            cpasync16(Bs + n * 80 + k8 * 2, (BT_PTR) + (size_t)n * (KDIM) + k0 + k8);  \
        }                                                                              \
    };                                                                                 \
    load_tile(0, smc);                                                                 \
    CP_COMMIT();                                                                       \
    load_tile(1, smc + STAGE_B);                                                       \
    CP_COMMIT();                                                                       \
    const uint32_t aRow = (uint32_t)((mBase + (g & 1) * 8 + rr) * 80)                  \
                        + (uint32_t)((g >> 1) * 16);                                   \
    const uint32_t bRow = (uint32_t)((nBase + (g >> 1) * 8 + rr) * 80)                 \
                        + (uint32_t)((g & 1) * 16);                                    \
    for (int kt = 0; kt < KT; kt++) {                                                  \
        CP_WAIT1();                                                                    \
        __syncthreads();                                                               \
        if (kt + 2 < KT) load_tile(kt + 2, smc + ((kt + 2) % 3) * STAGE_B);            \
        CP_COMMIT();                                                                   \
        uint32_t ab = smbase + (uint32_t)((kt % 3) * STAGE_B);                         \
        uint32_t bb2 = ab + 10240;                                                     \
        _Pragma("unroll")                                                              \
        for (int s = 0; s < 2; s++) {                                                  \
            uint32_t af[4][4];                                                         \
            uint32_t bq[4][4];                                                         \
            uint32_t aoff = ab + aRow + s * 32;                                        \
            uint32_t boff = bb2 + bRow + s * 32;                                       \
            _Pragma("unroll")                                                          \
            for (int mi = 0; mi < 4; mi++)                                             \
                LDMATRIX_X4(af[mi][0], af[mi][1], af[mi][2], af[mi][3],                \
                            aoff + mi * (16 * 80));                                    \
            _Pragma("unroll")                                                          \
            for (int p = 0; p < 4; p++)                                                \
                LDMATRIX_X4(bq[p][0], bq[p][1], bq[p][2], bq[p][3],                    \
                            boff + p * (16 * 80));                                     \
            _Pragma("unroll")                                                          \
            for (int mi = 0; mi < 4; mi++)                                             \
                _Pragma("unroll")                                                      \
                for (int nj = 0; nj < 8; nj++)                                         \
                    MMA_F16(ACC[mi][nj], af[mi][0], af[mi][1], af[mi][2], af[mi][3],   \
                            bq[nj >> 1][(nj & 1) * 2], bq[nj >> 1][(nj & 1) * 2 + 1]); \
        }                                                                              \
        __syncthreads();                                                               \
    }

// ---------------- generic fp16 GEMM (output projection): C fp32 ----------------
__global__ __launch_bounds__(256, 1) void gemm_f16(
        const __half* __restrict__ A, const __half* __restrict__ BT,
        float* __restrict__ C, int M, int Nn, int K) {
    extern __shared__ char smc[];
    const int bx = blockIdx.x, by = blockIdx.y;
    const __half* Ab = A  + (size_t)(by * 128) * K;
    const __half* Bb = BT + (size_t)(bx * 256) * K;

    float acc[4][8][4];
#pragma unroll
    for (int mi = 0; mi < 4; mi++)
#pragma unroll
        for (int nj = 0; nj < 8; nj++)
#pragma unroll
            for (int r = 0; r < 4; r++) acc[mi][nj][r] = 0.0f;

    GEMM_MAINLOOP(acc, Ab, Bb, K)

#pragma unroll
    for (int mi = 0; mi < 4; mi++) {
        int row = by * 128 + mBase + mi * 16 + gid;
#pragma unroll
        for (int nj = 0; nj < 8; nj++) {
            int col = bx * 256 + nBase + nj * 8 + tig * 2;
            *(float2*)(C + (size_t)row * Nn + col)       = make_float2(acc[mi][nj][0], acc[mi][nj][1]);
            *(float2*)(C + (size_t)(row + 8) * Nn + col) = make_float2(acc[mi][nj][2], acc[mi][nj][3]);
        }
    }
}

// ---------------- fused QKV GEMM + RoPE + ELU featurize ----------------
// CTA tile 128 x 256 (bx: 0-3 q, 4-7 k, 8-11 v; each tile = 4 heads).
#define ST_PITCH 264
__global__ __launch_bounds__(256, 1) void gemm_qkv(
        const __half* __restrict__ A, const __half* __restrict__ BT,
        __half* __restrict__ qh, __half* __restrict__ kh, __half* __restrict__ vh) {
    extern __shared__ char smc[];
    const int K = DIM;
    const int bx = blockIdx.x, by = blockIdx.y;
    const __half* Ab = A + (size_t)(by * 128) * K;
    const __half* Bb = BT + (size_t)(bx * 256) * K;

    float acc[4][8][4];
#pragma unroll
    for (int mi = 0; mi < 4; mi++)
#pragma unroll
        for (int nj = 0; nj < 8; nj++)
#pragma unroll
            for (int r = 0; r < 4; r++) acc[mi][nj][r] = 0.0f;

    GEMM_MAINLOOP(acc, Ab, Bb, K)

    // ---- epilogue: stage tile fp32, featurize, store fp16 ----
    float* St = (float*)smc;        // 128 x 264 floats = 135168 B
#pragma unroll
    for (int mi = 0; mi < 4; mi++) {
        int r = mBase + mi * 16 + gid;
#pragma unroll
        for (int nj = 0; nj < 8; nj++) {
            int ccol = nBase + nj * 8 + tig * 2;
            *(float2*)&St[r * ST_PITCH + ccol]       = make_float2(acc[mi][nj][0], acc[mi][nj][1]);
            *(float2*)&St[(r + 8) * ST_PITCH + ccol] = make_float2(acc[mi][nj][2], acc[mi][nj][3]);
        }
    }
    __syncthreads();

    const int sel   = bx >> 2;           // 0=q, 1=k, 2=v
    const int hbase = (bx & 3) * 4;      // 4 heads per tile
    const int d2    = (tid & 15) * 2;    // d pair base (0..30)
    const int hht   = (tid >> 4) & 3;    // head within tile
    const int rbase = tid >> 6;          // 0..3
    const int bb    = by >> 5;           // batch
    const int n0    = (by * 128) & 4095;

    __half* dst = (sel == 0) ? qh : ((sel == 1) ? kh : vh);
    float inv_fa = 0.0f, inv_fb = 0.0f;
    if (sel < 2) {
        inv_fa = (float)exp(-(double)d2 * (9.210340371976184 / 32.0));
        inv_fb = (float)exp(-(double)(d2 + 1) * (9.210340371976184 / 32.0));
    }

#pragma unroll 4
    for (int k = 0; k < 32; k++) {
        int row = rbase + k * 4;
        float2 xa = *(float2*)&St[row * ST_PITCH + hht * 64 + d2];        // d2, d2+1
        float2 xb = *(float2*)&St[row * ST_PITCH + hht * 64 + d2 + 32];   // d2+32, d2+33
        float f1a, f1b, f2a, f2b;
        if (sel == 2) {
            f1a = xa.x; f1b = xa.y; f2a = xb.x; f2b = xb.y;
        } else {
            float nrow = (float)(n0 + row);
            float sa, ca, sb, cb;
            rope_sincos_f(nrow * inv_fa, sa, ca);
            rope_sincos_f(nrow * inv_fb, sb, cb);
            float y1a = (xa.x * ca - xb.x * sa) * FEAT_SCALE;
            float y2a = (xa.x * sa + xb.x * ca) * FEAT_SCALE;
            float y1b = (xa.y * cb - xb.y * sb) * FEAT_SCALE;
            float y2b = (xa.y * sb + xb.y * cb) * FEAT_SCALE;
            f1a = (y1a > 0.0f) ? y1a + 1.0f : expf(y1a);
            f2a = (y2a > 0.0f) ? y2a + 1.0f : expf(y2a);
            f1b = (y1b > 0.0f) ? y1b + 1.0f : expf(y1b);
            f2b = (y2b > 0.0f) ? y2b + 1.0f : expf(y2b);
        }
        size_t ob = (((size_t)(bb * HEADS + hbase + hht)) * SEQ + (n0 + row)) * DH;
        *(__half2*)(dst + ob + d2)      = __floats2half2_rn(f1a, f1b);
        *(__half2*)(dst + ob + 32 + d2) = __floats2half2_rn(f2a, f2b);
    }
}

// ---------------- pass A: tensor-core per-chunk K^T V (64x64) and sum(k) ----------------
__global__ __launch_bounds__(256) void chunk_sums_tc(
        const __half* __restrict__ kh, const __half* __restrict__ vh,
        float* __restrict__ kvch, float* __restrict__ ksch) {
    extern __shared__ char smem[];
    __half* Kh = (__half*)smem;              // 128 x 144 B = 18432
    __half* Vh = (__half*)(smem + 18432);    // 18432

    const int blk = blockIdx.x;
    const int c  = blk % NCHUNK;
    const int bh = blk / NCHUNK;
    const int tid = threadIdx.x;
    const int warp = tid >> 5, lane = tid & 31;
    const int gid = lane >> 2, tig = lane & 3;
    const int g = lane >> 3, rr = lane & 7;

    size_t gbase = (((size_t)bh) * SEQ + (size_t)c * CHUNK) * DH;
    for (int i = tid; i < 1024; i += 256) {
        int row = i >> 3, c16 = (i & 7) * 16;
        *(float4*)((char*)Kh + row * 144 + c16) = ((const float4*)(kh + gbase))[i];
        *(float4*)((char*)Vh + row * 144 + c16) = ((const float4*)(vh + gbase))[i];
    }
    __syncthreads();

    const uint32_t kbase = smem_u32p(Kh);
    const uint32_t vbase = smem_u32p(Vh);
    const int d0 = (warp & 3) * 16;
    const int m0 = (warp >> 2) * 32;

    float acc[4][4];
#pragma unroll
    for (int nt = 0; nt < 4; nt++)
#pragma unroll
        for (int r = 0; r < 4; r++) acc[nt][r] = 0.0f;

    const uint32_t aAddr = (uint32_t)(((g >> 1) * 8 + rr) * 144 + (d0 + (g & 1) * 8) * 2);
    const uint32_t bAddr = (uint32_t)(((g & 1) * 8 + rr) * 144 + (m0 + (g >> 1) * 8) * 2);

#pragma unroll
    for (int ks = 0; ks < 8; ks++) {
        uint32_t a0, a1, a2, a3;
        LDMATRIX_X4_TRANS(a0, a1, a2, a3, kbase + aAddr + (uint32_t)(ks * 16 * 144));
#pragma unroll
        for (int p = 0; p < 2; p++) {
            uint32_t b0, b1, b2, b3;
            LDMATRIX_X4_TRANS(b0, b1, b2, b3,
                              vbase + bAddr + (uint32_t)(ks * 16 * 144) + (uint32_t)(p * 32));
            MMA_F16(acc[p * 2],     a0, a1, a2, a3, b0, b1);
            MMA_F16(acc[p * 2 + 1], a0, a1, a2, a3, b2, b3);
        }
    }

    size_t obase = ((size_t)bh * NCHUNK + c) * (DH * DH);
    int row_lo = d0 + gid, row_hi = row_lo + 8;
#pragma unroll
    for (int nt = 0; nt < 4; nt++) {
        int col = m0 + nt * 8 + tig * 2;
        *(float2*)&kvch[obase + (size_t)row_lo * 64 + col] = make_float2(acc[nt][0], acc[nt][1]);
        *(float2*)&kvch[obase + (size_t)row_hi * 64 + col] = make_float2(acc[nt][2], acc[nt][3]);
    }

    if (tid < 64) {
        float ssum = 0.0f;
        for (int r = 0; r < 128; r++)
            ssum += __half2float(Kh[r * 72 + tid]);
        ksch[((size_t)bh * NCHUNK + c) * DH + tid] = ssum;
    }
}

// ---------------- pass B: exclusive prefix over chunks (in place) ----------------
__global__ void prefix_kernel(float* __restrict__ kvch, float* __restrict__ ksch) {
    int bh = blockIdx.x;
    for (int e = threadIdx.x; e < DH * DH; e += blockDim.x) {
        float acc = 0.0f;
        for (int c = 0; c < NCHUNK; c++) {
            float* p = &kvch[((size_t)bh * NCHUNK + c) * (DH * DH) + e];
            float t = *p; *p = acc; acc += t;
        }
    }
    for (int e = threadIdx.x; e < DH; e += blockDim.x) {
        float acc = 0.0f;
        for (int c = 0; c < NCHUNK; c++) {
            float* p = &ksch[((size_t)bh * NCHUNK + c) * DH + e];
            float t = *p; *p = acc; acc += t;
        }
    }
}

// ---------------- pass C: tensor-core per-chunk output ----------------
#define PQU 36
#define PSU 68
__global__ __launch_bounds__(256) void chunk_out_tc(
        const __half* __restrict__ qh, const __half* __restrict__ kh,
        const __half* __restrict__ vh, const float* __restrict__ kvch,
        const float* __restrict__ ksch, __half* __restrict__ attn) {
    extern __shared__ char smem[];
    __half* Qh   = (__half*)smem;
    __half* Kh   = (__half*)(smem + 18432);
    __half* Vh   = (__half*)(smem + 36864);
    __half* KVph = (__half*)(smem + 55296);
    __half* Sh   = (__half*)(smem + 64512);
    float* rowsum = (float*)(smem + 99328);
    float* den    = (float*)(smem + 99840);
    float* KSp    = (float*)(smem + 100352);

    const int blk = blockIdx.x;
    const int c  = blk % NCHUNK;
    const int bh = blk / NCHUNK;
    const int b  = bh / HEADS;
    const int h  = bh % HEADS;
    const int tid = threadIdx.x;
    const int warp = tid >> 5, lane = tid & 31;
    const int gid = lane >> 2, tig = lane & 3;
    const int g = lane >> 3, rr = lane & 7;

    size_t gbase = (((size_t)bh) * SEQ + (size_t)c * CHUNK) * DH;
    for (int i = tid; i < 1024; i += 256) {
        int row = i >> 3, c16 = (i & 7) * 16;
        *(float4*)((char*)Qh + row * 144 + c16) = ((const float4*)(qh + gbase))[i];
        *(float4*)((char*)Kh + row * 144 + c16) = ((const float4*)(kh + gbase))[i];
        *(float4*)((char*)Vh + row * 144 + c16) = ((const float4*)(vh + gbase))[i];
    }
    {
        size_t kvbase = ((size_t)bh * NCHUNK + c) * (DH * DH);
        for (int i = tid; i < 2048; i += 256) {
            int d = i >> 5, m2 = i & 31;
            float2 f = ((const float2*)(kvch + kvbase))[i];
            *(uint32_t*)((char*)KVph + d * 144 + m2 * 4) =
                h2_to_u32(__floats2half2_rn(f.x, f.y));
        }
        if (tid < 64)
            KSp[tid] = ksch[((size_t)bh * NCHUNK + c) * DH + tid];
    }
    __syncthreads();

    const uint32_t* Qu = (const uint32_t*)Qh;
    uint32_t* Su = (uint32_t*)Sh;
    const uint32_t qbase = smem_u32p(Qh);
    const uint32_t kbase = smem_u32p(Kh);
    const uint32_t sbase = smem_u32p(Sh);
    const int r0 = warp * 16;

    const uint32_t aRowQ = (uint32_t)((r0 + (g & 1) * 8 + rr) * 144 + (g >> 1) * 16);
    const uint32_t aRowS = (uint32_t)((r0 + (g & 1) * 8 + rr) * 272 + (g >> 1) * 16);
    const uint32_t bRowK = (uint32_t)(((g >> 1) * 8 + rr) * 144 + (g & 1) * 16);

    {
        float acc1[16][4];
#pragma unroll
        for (int nt = 0; nt < 16; nt++)
#pragma unroll
            for (int r = 0; r < 4; r++) acc1[nt][r] = 0.0f;

#pragma unroll
        for (int ks = 0; ks < 4; ks++) {
            uint32_t aq[4];
            LDMATRIX_X4(aq[0], aq[1], aq[2], aq[3], qbase + aRowQ + ks * 32);
#pragma unroll
            for (int p = 0; p < 8; p++) {
                uint32_t bk[4];
                LDMATRIX_X4(bk[0], bk[1], bk[2], bk[3],
                            kbase + bRowK + (uint32_t)(p * 16 * 144) + ks * 32);
                MMA_F16(acc1[2 * p],     aq[0], aq[1], aq[2], aq[3], bk[0], bk[1]);
                MMA_F16(acc1[2 * p + 1], aq[0], aq[1], aq[2], aq[3], bk[2], bk[3]);
            }
        }

        int row_lo = r0 + gid, row_hi = row_lo + 8;
        float sum_lo = 0.0f, sum_hi = 0.0f;
#pragma unroll
        for (int nt = 0; nt < 16; nt++) {
            int c0 = nt * 8 + tig * 2, c1 = c0 + 1;
            float v0 = (c0 <= row_lo) ? acc1[nt][0] : 0.0f;
            float v1 = (c1 <= row_lo) ? acc1[nt][1] : 0.0f;
            float v2 = (c0 <= row_hi) ? acc1[nt][2] : 0.0f;
            float v3 = (c1 <= row_hi) ? acc1[nt][3] : 0.0f;
            sum_lo += v0 + v1;
            sum_hi += v2 + v3;
            Su[row_lo * PSU + nt * 4 + tig] = h2_to_u32(__floats2half2_rn(v0, v1));
            Su[row_hi * PSU + nt * 4 + tig] = h2_to_u32(__floats2half2_rn(v2, v3));
        }
        sum_lo += __shfl_xor_sync(0xffffffff, sum_lo, 1);
        sum_lo += __shfl_xor_sync(0xffffffff, sum_lo, 2);
        sum_hi += __shfl_xor_sync(0xffffffff, sum_hi, 1);
        sum_hi += __shfl_xor_sync(0xffffffff, sum_hi, 2);
        if (tig == 0) { rowsum[row_lo] = sum_lo; rowsum[row_hi] = sum_hi; }
    }
    __syncthreads();

    if (tid < 128) {
        float dsum = rowsum[tid];
        const uint32_t* Qr = Qu + tid * PQU;
#pragma unroll
        for (int dd = 0; dd < 32; dd++) {
            float2 qv = __half22float2(u32_to_h2(Qr[dd]));
            dsum += qv.x * KSp[dd * 2] + qv.y * KSp[dd * 2 + 1];
        }
        den[tid] = 1.0f / fmaxf(dsum, 1e-6f);
    }
    __syncthreads();

    {
        float acc2[8][4];
#pragma unroll
        for (int nt = 0; nt < 8; nt++)
#pragma unroll
            for (int r = 0; r < 4; r++) acc2[nt][r] = 0.0f;

        const uint32_t vbase = smem_u32p(Vh);
        const uint32_t kvbase = smem_u32p(KVph);
        const int sel = lane >> 3;
        const int srow_in = ((sel & 1) << 3) + (lane & 7);
        const int ncol_in = (sel >> 1) << 3;

#pragma unroll
        for (int ks = 0; ks < 8; ks++) {
            uint32_t as[4];
            LDMATRIX_X4(as[0], as[1], as[2], as[3], sbase + aRowS + ks * 32);
#pragma unroll
            for (int nt2 = 0; nt2 < 4; nt2++) {
                uint32_t addr = vbase + (uint32_t)((ks * 16 + srow_in) * 144 + (nt2 * 16 + ncol_in) * 2);
                uint32_t b0, b1, b2, b3;
                LDMATRIX_X4_TRANS(b0, b1, b2, b3, addr);
                MMA_F16(acc2[nt2 * 2],     as[0], as[1], as[2], as[3], b0, b1);
                MMA_F16(acc2[nt2 * 2 + 1], as[0], as[1], as[2], as[3], b2, b3);
            }
        }
#pragma unroll
        for (int ks = 0; ks < 4; ks++) {
            uint32_t aq[4];
            LDMATRIX_X4(aq[0], aq[1], aq[2], aq[3], qbase + aRowQ + ks * 32);
#pragma unroll
            for (int nt2 = 0; nt2 < 4; nt2++) {
                uint32_t addr = kvbase + (uint32_t)((ks * 16 + srow_in) * 144 + (nt2 * 16 + ncol_in) * 2);
                uint32_t b0, b1, b2, b3;
                LDMATRIX_X4_TRANS(b0, b1, b2, b3, addr);
                MMA_F16(acc2[nt2 * 2],     aq[0], aq[1], aq[2], aq[3], b0, b1);
                MMA_F16(acc2[nt2 * 2 + 1], aq[0], aq[1], aq[2], aq[3], b2, b3);
            }
        }

        int row_lo = r0 + gid, row_hi = row_lo + 8;
        float inv_lo = den[row_lo], inv_hi = den[row_hi];
        size_t obL = ((size_t)b * SEQ + (size_t)c * CHUNK + row_lo) * DIM + h * 64;
        size_t obH = obL + (size_t)8 * DIM;
#pragma unroll
        for (int nt = 0; nt < 8; nt++) {
            int c0 = nt * 8 + tig * 2;
            *(__half2*)(attn + obL + c0) = __floats2half2_rn(acc2[nt][0] * inv_lo, acc2[nt][1] * inv_lo);
            *(__half2*)(attn + obH + c0) = __floats2half2_rn(acc2[nt][2] * inv_hi, acc2[nt][3] * inv_hi);
        }
    }
}

// ---------------- host launch ----------------
extern "C" void kernel_launch(void* const* d_in, const int* in_sizes, int n_in,
                              void* d_out, int out_size) {
    const float* x    = (const float*)d_in[0];
    const float* wqkv = (const float*)d_in[1];
    const float* wout = (const float*)d_in[2];
    float* out = (float*)d_out;

    float *kvch, *ksch;
    __half *xh, *wqkvT, *woutT, *qh, *kh, *vh, *attnh;
    cudaGetSymbolAddress((void**)&xh,    g_xh);
    cudaGetSymbolAddress((void**)&wqkvT, g_wqkvT);
    cudaGetSymbolAddress((void**)&woutT, g_woutT);
    cudaGetSymbolAddress((void**)&qh,    g_qh);
    cudaGetSymbolAddress((void**)&kh,    g_kh);
    cudaGetSymbolAddress((void**)&vh,    g_vh);
    cudaGetSymbolAddress((void**)&attnh, g_attnh);
    cudaGetSymbolAddress((void**)&kvch,  g_kvch);
    cudaGetSymbolAddress((void**)&ksch,  g_ksch);

    const size_t smemG  = 3 * STAGE_B;                 // 92160 B
    const size_t smemGQ = 128 * ST_PITCH * sizeof(float); // 135168 B (covers pipeline too)
    const size_t smemS  = 2 * 18432;
    const size_t smemC  = 100608;
    cudaFuncSetAttribute(gemm_f16,      cudaFuncAttributeMaxDynamicSharedMemorySize, (int)smemG);
    cudaFuncSetAttribute(gemm_qkv,      cudaFuncAttributeMaxDynamicSharedMemorySize, (int)smemGQ);
    cudaFuncSetAttribute(chunk_sums_tc, cudaFuncAttributeMaxDynamicSharedMemorySize, (int)smemS);
    cudaFuncSetAttribute(chunk_out_tc,  cudaFuncAttributeMaxDynamicSharedMemorySize, (int)smemC);

    // 0) fp16 conversions
    {
        int n2x = (BATCH * SEQ * DIM) / 2;
        f32_to_f16_kernel<<<(n2x + 255) / 256, 256>>>((const float2*)x, (__half2*)xh, n2x);
        transpose_f16<<<dim3(3 * DIM / 32, DIM / 32), dim3(32, 8)>>>(wqkv, wqkvT, DIM, 3 * DIM);
        transpose_f16<<<dim3(DIM / 32, DIM / 32), dim3(32, 8)>>>(wout, woutT, DIM, DIM);
    }

    // 1) fused qkv GEMM + RoPE + ELU -> fp16 q/k/v  (CTA 128x256)
    gemm_qkv<<<dim3(3072 / 256, 16384 / 128), 256, smemGQ>>>(xh, wqkvT, qh, kh, vh);
    // 2) per-chunk K^T V sums
    chunk_sums_tc<<<BH * NCHUNK, 256, smemS>>>(kh, vh, kvch, ksch);
    // 3) exclusive prefix across chunks
    prefix_kernel<<<BH, 1024>>>(kvch, ksch);
    // 4) per-chunk outputs via tensor cores
    chunk_out_tc<<<BH * NCHUNK, 256, smemC>>>(qh, kh, vh, kvch, ksch, attnh);
    // 5) final = attnh @ woutT^T  (CTA 128x256)
    gemm_f16<<<dim3(1024 / 256, 16384 / 128), 256, smemG>>>(attnh, woutT, out, BATCH * SEQ, DIM, DIM);
}

// round 12
// speedup vs baseline: 1.1334x; 1.1334x over previous
#include <cuda_runtime.h>
#include <cuda_fp16.h>
#include <math.h>
#include <stdint.h>

#define BATCH 4
#define SEQ   4096
#define DIM   1024
#define HEADS 16
#define DH    64
#define CHUNK 128
#define NCHUNK 32
#define BH    (BATCH*HEADS)
#define FEAT_SCALE 0.35355339059327373f  // 64^-0.25

// ---------------- scratch (device globals; no allocation allowed) ----------------
__device__ __half g_xh   [BATCH*SEQ*DIM];     // fp16 x
__device__ __half g_wqkvT[3*DIM*DIM];         // K-major fp16
__device__ __half g_woutT[DIM*DIM];           // K-major fp16
__device__ __half g_qh  [BH*SEQ*DH];          // featurized q (fp16)
__device__ __half g_kh  [BH*SEQ*DH];          // featurized k (fp16)
__device__ __half g_vh  [BH*SEQ*DH];          // v (fp16)
__device__ __half g_attnh[BATCH*SEQ*DIM];     // attention out, fp16
__device__ float  g_kvch[BH*NCHUNK*DH*DH];
__device__ float  g_ksch[BH*NCHUNK*DH];

// ---------------- helpers ----------------
__device__ __forceinline__ uint32_t h2_to_u32(__half2 h) {
    __half2_raw r = *(__half2_raw*)&h;
    return (uint32_t)r.x | ((uint32_t)r.y << 16);
}
__device__ __forceinline__ __half2 u32_to_h2(uint32_t u) {
    __half2_raw r;
    r.x = (unsigned short)(u & 0xFFFF);
    r.y = (unsigned short)(u >> 16);
    return *(__half2*)&r;
}
__device__ __forceinline__ void cpasync16(void* dst, const void* src) {
    unsigned d = (unsigned)__cvta_generic_to_shared(dst);
    asm volatile("cp.async.ca.shared.global [%0], [%1], 16;" :: "r"(d), "l"(src));
}
#define CP_COMMIT()  asm volatile("cp.async.commit_group;")
#define CP_WAIT1()   asm volatile("cp.async.wait_group 1;")

#define MMA_F16(acc, a0, a1, a2, a3, b0, b1) \
    asm volatile("mma.sync.aligned.m16n8k16.row.col.f32.f16.f16.f32 " \
        "{%0,%1,%2,%3}, {%4,%5,%6,%7}, {%8,%9}, {%0,%1,%2,%3};" \
        : "+f"((acc)[0]), "+f"((acc)[1]), "+f"((acc)[2]), "+f"((acc)[3]) \
        : "r"(a0), "r"(a1), "r"(a2), "r"(a3), "r"(b0), "r"(b1))

#define LDMATRIX_X4(r0, r1, r2, r3, addr) \
    asm volatile("ldmatrix.sync.aligned.m8n8.x4.shared.b16 {%0,%1,%2,%3}, [%4];" \
        : "=r"(r0), "=r"(r1), "=r"(r2), "=r"(r3) : "r"(addr))

#define LDMATRIX_X4_TRANS(r0, r1, r2, r3, addr) \
    asm volatile("ldmatrix.sync.aligned.m8n8.x4.trans.shared.b16 {%0,%1,%2,%3}, [%4];" \
        : "=r"(r0), "=r"(r1), "=r"(r2), "=r"(r3) : "r"(addr))

__device__ __forceinline__ uint32_t smem_u32p(const void* p) {
    return (uint32_t)__cvta_generic_to_shared(p);
}

// fp32 sincos, FMA Cody-Waite range reduction (accurate ~1e-7 for ang < 5000)
__device__ __forceinline__ void rope_sincos_f(float ang, float& s, float& c) {
    float qf = rintf(ang * 0.63661977f);
    float r = fmaf(-qf, 1.57079637e+0f, ang);
    r = fmaf(qf, 4.37113900e-8f, r);
    int qi = (int)qf & 3;
    float r2 = r * r;
    float sp = r * (1.0f + r2 * (-1.6666667e-1f + r2 * (8.3333337e-3f
              + r2 * (-1.9841270e-4f + r2 * 2.7557319e-6f))));
    float cp = 1.0f + r2 * (-0.5f + r2 * (4.1666668e-2f
              + r2 * (-1.3888889e-3f + r2 * 2.4801587e-5f)));
    switch (qi) {
        case 0:  s =  sp; c =  cp; break;
        case 1:  s =  cp; c = -sp; break;
        case 2:  s = -sp; c = -cp; break;
        default: s = -cp; c =  sp; break;
    }
}

// ---------------- fp16 conversion pre-passes ----------------
__global__ void f32_to_f16_kernel(const float2* __restrict__ in, __half2* __restrict__ out, int n2) {
    int i = blockIdx.x * blockDim.x + threadIdx.x;
    if (i < n2) out[i] = __float22half2_rn(in[i]);
}

__global__ void transpose_f16(const float* __restrict__ W, __half* __restrict__ WT,
                              int K, int Nn) {
    __shared__ float t[32][33];
    int n0 = blockIdx.x * 32, k0 = blockIdx.y * 32;
    int tx = threadIdx.x, ty = threadIdx.y;
#pragma unroll
    for (int i = 0; i < 32; i += 8)
        t[ty + i][tx] = W[(size_t)(k0 + ty + i) * Nn + n0 + tx];
    __syncthreads();
#pragma unroll
    for (int i = 0; i < 32; i += 8)
        WT[(size_t)(n0 + ty + i) * K + k0 + tx] = __float2half(t[tx][ty + i]);
}

// ---------------- generic fp16 GEMM (R10 geometry; single sync/iter) ----------------
#define STAGE_B 20480      // bytes per stage: A 10240 + B 10240 (pitch 80 B)
__global__ __launch_bounds__(256) void gemm_f16(
        const __half* __restrict__ A, const __half* __restrict__ BT,
        float* __restrict__ C, int M, int Nn, int K) {
    extern __shared__ char smc[];
    const int tid = threadIdx.x;
    const int bx = blockIdx.x, by = blockIdx.y;
    const int warp = tid >> 5, lane = tid & 31;
    const int gid = lane >> 2, tig = lane & 3;
    const int g = lane >> 3, rr = lane & 7;
    const int warpM = warp & 1, warpN = warp >> 1;
    const int mBase = warpM * 64;
    const int nBase = warpN * 32;

    const __half* Ab = A  + (size_t)(by * 128) * K;
    const __half* Bb = BT + (size_t)(bx * 128) * K;
    const uint32_t smbase = smem_u32p(smc);

    float acc[4][4][4];
#pragma unroll
    for (int mi = 0; mi < 4; mi++)
#pragma unroll
        for (int nj = 0; nj < 4; nj++)
#pragma unroll
            for (int r = 0; r < 4; r++) acc[mi][nj][r] = 0.0f;

    const int KT = K >> 5;

    auto load_tile = [&](int kt, char* buf) {
        char* As = buf;
        char* Bs = buf + 10240;
        int k0 = kt * 32;
#pragma unroll
        for (int i = 0; i < 2; i++) {
            int c = i * 256 + tid;
            int m = c >> 2, k8 = (c & 3) * 8;
            cpasync16(As + m * 80 + k8 * 2, Ab + (size_t)m * K + k0 + k8);
        }
#pragma unroll
        for (int i = 0; i < 2; i++) {
            int c = i * 256 + tid;
            int n = c >> 2, k8 = (c & 3) * 8;
            cpasync16(Bs + n * 80 + k8 * 2, Bb + (size_t)n * K + k0 + k8);
        }
    };

    load_tile(0, smc);
    CP_COMMIT();
    load_tile(1, smc + STAGE_B);
    CP_COMMIT();

    const uint32_t aRow = (uint32_t)((mBase + (g & 1) * 8 + rr) * 80) + (uint32_t)((g >> 1) * 16);
    const uint32_t bRow = (uint32_t)((nBase + (g >> 1) * 8 + rr) * 80) + (uint32_t)((g & 1) * 16);

    for (int kt = 0; kt < KT; kt++) {
        CP_WAIT1();
        __syncthreads();            // stage kt visible CTA-wide; all warps past compute kt-1
        if (kt + 2 < KT) load_tile(kt + 2, smc + ((kt + 2) % 3) * STAGE_B);
        CP_COMMIT();

        uint32_t ab = smbase + (uint32_t)((kt % 3) * STAGE_B);
        uint32_t bb = ab + 10240;

#pragma unroll
        for (int s = 0; s < 2; s++) {
            uint32_t af[4][4];
            uint32_t bq[2][4];
            uint32_t aoff = ab + aRow + s * 32;
            uint32_t boff = bb + bRow + s * 32;
#pragma unroll
            for (int mi = 0; mi < 4; mi++)
                LDMATRIX_X4(af[mi][0], af[mi][1], af[mi][2], af[mi][3], aoff + mi * (16 * 80));
#pragma unroll
            for (int p = 0; p < 2; p++)
                LDMATRIX_X4(bq[p][0], bq[p][1], bq[p][2], bq[p][3], boff + p * (16 * 80));
#pragma unroll
            for (int mi = 0; mi < 4; mi++)
#pragma unroll
                for (int nj = 0; nj < 4; nj++)
                    MMA_F16(acc[mi][nj], af[mi][0], af[mi][1], af[mi][2], af[mi][3],
                            bq[nj >> 1][(nj & 1) * 2], bq[nj >> 1][(nj & 1) * 2 + 1]);
        }
        // no trailing sync: next iteration's top sync provides the hazard fence
    }

#pragma unroll
    for (int mi = 0; mi < 4; mi++) {
        int row = by * 128 + mBase + mi * 16 + gid;
#pragma unroll
        for (int nj = 0; nj < 4; nj++) {
            int col = bx * 128 + nBase + nj * 8 + tig * 2;
            *(float2*)(C + (size_t)row * Nn + col)       = make_float2(acc[mi][nj][0], acc[mi][nj][1]);
            *(float2*)(C + (size_t)(row + 8) * Nn + col) = make_float2(acc[mi][nj][2], acc[mi][nj][3]);
        }
    }
}

// ---------------- fused QKV GEMM + RoPE + ELU featurize (R10 geometry) ----------------
__global__ __launch_bounds__(256) void gemm_qkv(
        const __half* __restrict__ A, const __half* __restrict__ BT,
        __half* __restrict__ qh, __half* __restrict__ kh, __half* __restrict__ vh) {
    extern __shared__ char smc[];
    const int K = DIM;
    const int tid = threadIdx.x;
    const int bx = blockIdx.x, by = blockIdx.y;
    const int warp = tid >> 5, lane = tid & 31;
    const int gid = lane >> 2, tig = lane & 3;
    const int g = lane >> 3, rr = lane & 7;
    const int warpM = warp & 1, warpN = warp >> 1;
    const int mBase = warpM * 64;
    const int nBase = warpN * 32;

    const __half* Ab = A + (size_t)(by * 128) * K;
    const __half* Bb = BT + (size_t)(bx * 128) * K;
    const uint32_t smbase = smem_u32p(smc);

    float acc[4][4][4];
#pragma unroll
    for (int mi = 0; mi < 4; mi++)
#pragma unroll
        for (int nj = 0; nj < 4; nj++)
#pragma unroll
            for (int r = 0; r < 4; r++) acc[mi][nj][r] = 0.0f;

    const int KT = K >> 5;

    auto load_tile = [&](int kt, char* buf) {
        char* As = buf;
        char* Bs = buf + 10240;
        int k0 = kt * 32;
#pragma unroll
        for (int i = 0; i < 2; i++) {
            int c = i * 256 + tid;
            int m = c >> 2, k8 = (c & 3) * 8;
            cpasync16(As + m * 80 + k8 * 2, Ab + (size_t)m * K + k0 + k8);
        }
#pragma unroll
        for (int i = 0; i < 2; i++) {
            int c = i * 256 + tid;
            int n = c >> 2, k8 = (c & 3) * 8;
            cpasync16(Bs + n * 80 + k8 * 2, Bb + (size_t)n * K + k0 + k8);
        }
    };

    load_tile(0, smc);
    CP_COMMIT();
    load_tile(1, smc + STAGE_B);
    CP_COMMIT();

    const uint32_t aRow = (uint32_t)((mBase + (g & 1) * 8 + rr) * 80) + (uint32_t)((g >> 1) * 16);
    const uint32_t bRow = (uint32_t)((nBase + (g >> 1) * 8 + rr) * 80) + (uint32_t)((g & 1) * 16);

    for (int kt = 0; kt < KT; kt++) {
        CP_WAIT1();
        __syncthreads();
        if (kt + 2 < KT) load_tile(kt + 2, smc + ((kt + 2) % 3) * STAGE_B);
        CP_COMMIT();

        uint32_t ab = smbase + (uint32_t)((kt % 3) * STAGE_B);
        uint32_t bb = ab + 10240;

#pragma unroll
        for (int s = 0; s < 2; s++) {
            uint32_t af[4][4];
            uint32_t bq[2][4];
            uint32_t aoff = ab + aRow + s * 32;
            uint32_t boff = bb + bRow + s * 32;
#pragma unroll
            for (int mi = 0; mi < 4; mi++)
                LDMATRIX_X4(af[mi][0], af[mi][1], af[mi][2], af[mi][3], aoff + mi * (16 * 80));
#pragma unroll
            for (int p = 0; p < 2; p++)
                LDMATRIX_X4(bq[p][0], bq[p][1], bq[p][2], bq[p][3], boff + p * (16 * 80));
#pragma unroll
            for (int mi = 0; mi < 4; mi++)
#pragma unroll
                for (int nj = 0; nj < 4; nj++)
                    MMA_F16(acc[mi][nj], af[mi][0], af[mi][1], af[mi][2], af[mi][3],
                            bq[nj >> 1][(nj & 1) * 2], bq[nj >> 1][(nj & 1) * 2 + 1]);
        }
    }

    // ---- epilogue: stage tile fp32, featurize, store fp16 ----
    __syncthreads();                 // all warps done with pipeline buffers before reuse
    float* St = (float*)smc;         // 128 x pitch 132 floats = 67584 B
#pragma unroll
    for (int mi = 0; mi < 4; mi++) {
        int r = mBase + mi * 16 + gid;
#pragma unroll
        for (int nj = 0; nj < 4; nj++) {
            int ccol = nBase + nj * 8 + tig * 2;
            *(float2*)&St[r * 132 + ccol]       = make_float2(acc[mi][nj][0], acc[mi][nj][1]);
            *(float2*)&St[(r + 8) * 132 + ccol] = make_float2(acc[mi][nj][2], acc[mi][nj][3]);
        }
    }
    __syncthreads();

    const int sel   = bx >> 3;           // 0=q, 1=k, 2=v
    const int hbase = (bx & 7) * 2;
    const int d     = tid & 31;
    const int hh    = (tid >> 5) & 1;
    const int rbase = tid >> 6;          // 0..3
    const int bb    = by >> 5;           // batch
    const int n0    = (by * 128) & 4095;

    __half* dst = (sel == 0) ? qh : ((sel == 1) ? kh : vh);
    float inv_f = (sel < 2) ? (float)exp(-(double)d * (9.210340371976184 / 32.0)) : 0.0f;

#pragma unroll 4
    for (int k = 0; k < 32; k++) {
        int row = rbase + k * 4;
        float x1 = St[row * 132 + hh * 64 + d];
        float x2 = St[row * 132 + hh * 64 + d + 32];
        float f1, f2;
        if (sel == 2) {
            f1 = x1; f2 = x2;
        } else {
            float ang = (float)(n0 + row) * inv_f;
            float s, c;
            rope_sincos_f(ang, s, c);
            float y1 = (x1 * c - x2 * s) * FEAT_SCALE;
            float y2 = (x1 * s + x2 * c) * FEAT_SCALE;
            f1 = (y1 > 0.0f) ? y1 + 1.0f : expf(y1);
            f2 = (y2 > 0.0f) ? y2 + 1.0f : expf(y2);
        }
        size_t ob = (((size_t)(bb * HEADS + hbase + hh)) * SEQ + (n0 + row)) * DH + d;
        dst[ob]      = __float2half(f1);
        dst[ob + 32] = __float2half(f2);
    }
}

// ---------------- pass A: tensor-core per-chunk K^T V (64x64) and sum(k) ----------------
__global__ __launch_bounds__(256) void chunk_sums_tc(
        const __half* __restrict__ kh, const __half* __restrict__ vh,
        float* __restrict__ kvch, float* __restrict__ ksch) {
    extern __shared__ char smem[];
    __half* Kh = (__half*)smem;              // 128 x 144 B = 18432
    __half* Vh = (__half*)(smem + 18432);    // 18432

    const int blk = blockIdx.x;
    const int c  = blk % NCHUNK;
    const int bh = blk / NCHUNK;
    const int tid = threadIdx.x;
    const int warp = tid >> 5, lane = tid & 31;
    const int gid = lane >> 2, tig = lane & 3;
    const int g = lane >> 3, rr = lane & 7;

    size_t gbase = (((size_t)bh) * SEQ + (size_t)c * CHUNK) * DH;
    for (int i = tid; i < 1024; i += 256) {
        int row = i >> 3, c16 = (i & 7) * 16;
        *(float4*)((char*)Kh + row * 144 + c16) = ((const float4*)(kh + gbase))[i];
        *(float4*)((char*)Vh + row * 144 + c16) = ((const float4*)(vh + gbase))[i];
    }
    __syncthreads();

    const uint32_t kbase = smem_u32p(Kh);
    const uint32_t vbase = smem_u32p(Vh);
    const int d0 = (warp & 3) * 16;
    const int m0 = (warp >> 2) * 32;

    float acc[4][4];
#pragma unroll
    for (int nt = 0; nt < 4; nt++)
#pragma unroll
        for (int r = 0; r < 4; r++) acc[nt][r] = 0.0f;

    const uint32_t aAddr = (uint32_t)(((g >> 1) * 8 + rr) * 144 + (d0 + (g & 1) * 8) * 2);
    const uint32_t bAddr = (uint32_t)(((g & 1) * 8 + rr) * 144 + (m0 + (g >> 1) * 8) * 2);

#pragma unroll
    for (int ks = 0; ks < 8; ks++) {
        uint32_t a0, a1, a2, a3;
        LDMATRIX_X4_TRANS(a0, a1, a2, a3, kbase + aAddr + (uint32_t)(ks * 16 * 144));
#pragma unroll
        for (int p = 0; p < 2; p++) {
            uint32_t b0, b1, b2, b3;
            LDMATRIX_X4_TRANS(b0, b1, b2, b3,
                              vbase + bAddr + (uint32_t)(ks * 16 * 144) + (uint32_t)(p * 32));
            MMA_F16(acc[p * 2],     a0, a1, a2, a3, b0, b1);
            MMA_F16(acc[p * 2 + 1], a0, a1, a2, a3, b2, b3);
        }
    }

    size_t obase = ((size_t)bh * NCHUNK + c) * (DH * DH);
    int row_lo = d0 + gid, row_hi = row_lo + 8;
#pragma unroll
    for (int nt = 0; nt < 4; nt++) {
        int col = m0 + nt * 8 + tig * 2;
        *(float2*)&kvch[obase + (size_t)row_lo * 64 + col] = make_float2(acc[nt][0], acc[nt][1]);
        *(float2*)&kvch[obase + (size_t)row_hi * 64 + col] = make_float2(acc[nt][2], acc[nt][3]);
    }

    if (tid < 64) {
        float ssum = 0.0f;
        for (int r = 0; r < 128; r++)
            ssum += __half2float(Kh[r * 72 + tid]);
        ksch[((size_t)bh * NCHUNK + c) * DH + tid] = ssum;
    }
}

// ---------------- pass B: exclusive prefix over chunks (batched loads, MLP=32) ----------------
__global__ void prefix_kernel(float* __restrict__ kvch, float* __restrict__ ksch) {
    int bh = blockIdx.x;
    for (int e = threadIdx.x; e < DH * DH; e += blockDim.x) {
        float* p = &kvch[(size_t)bh * NCHUNK * (DH * DH) + e];
        float r[NCHUNK];
#pragma unroll
        for (int c = 0; c < NCHUNK; c++) r[c] = p[(size_t)c * (DH * DH)];
        float acc = 0.0f;
#pragma unroll
        for (int c = 0; c < NCHUNK; c++) {
            float t = r[c];
            p[(size_t)c * (DH * DH)] = acc;
            acc += t;
        }
    }
    if (threadIdx.x < DH) {
        float* p = &ksch[(size_t)bh * NCHUNK * DH + threadIdx.x];
        float r[NCHUNK];
#pragma unroll
        for (int c = 0; c < NCHUNK; c++) r[c] = p[(size_t)c * DH];
        float acc = 0.0f;
#pragma unroll
        for (int c = 0; c < NCHUNK; c++) {
            float t = r[c];
            p[(size_t)c * DH] = acc;
            acc += t;
        }
    }
}

// ---------------- pass C: tensor-core per-chunk output ----------------
#define PQU 36
#define PSU 68
__global__ __launch_bounds__(256) void chunk_out_tc(
        const __half* __restrict__ qh, const __half* __restrict__ kh,
        const __half* __restrict__ vh, const float* __restrict__ kvch,
        const float* __restrict__ ksch, __half* __restrict__ attn) {
    extern __shared__ char smem[];
    __half* Qh   = (__half*)smem;
    __half* Kh   = (__half*)(smem + 18432);
    __half* Vh   = (__half*)(smem + 36864);
    __half* KVph = (__half*)(smem + 55296);
    __half* Sh   = (__half*)(smem + 64512);
    float* rowsum = (float*)(smem + 99328);
    float* den    = (float*)(smem + 99840);
    float* KSp    = (float*)(smem + 100352);

    const int blk = blockIdx.x;
    const int c  = blk % NCHUNK;
    const int bh = blk / NCHUNK;
    const int b  = bh / HEADS;
    const int h  = bh % HEADS;
    const int tid = threadIdx.x;
    const int warp = tid >> 5, lane = tid & 31;
    const int gid = lane >> 2, tig = lane & 3;
    const int g = lane >> 3, rr = lane & 7;

    size_t gbase = (((size_t)bh) * SEQ + (size_t)c * CHUNK) * DH;
    for (int i = tid; i < 1024; i += 256) {
        int row = i >> 3, c16 = (i & 7) * 16;
        *(float4*)((char*)Qh + row * 144 + c16) = ((const float4*)(qh + gbase))[i];
        *(float4*)((char*)Kh + row * 144 + c16) = ((const float4*)(kh + gbase))[i];
        *(float4*)((char*)Vh + row * 144 + c16) = ((const float4*)(vh + gbase))[i];
    }
    {
        size_t kvbase = ((size_t)bh * NCHUNK + c) * (DH * DH);
        for (int i = tid; i < 2048; i += 256) {
            int d = i >> 5, m2 = i & 31;
            float2 f = ((const float2*)(kvch + kvbase))[i];
            *(uint32_t*)((char*)KVph + d * 144 + m2 * 4) =
                h2_to_u32(__floats2half2_rn(f.x, f.y));
        }
        if (tid < 64)
            KSp[tid] = ksch[((size_t)bh * NCHUNK + c) * DH + tid];
    }
    __syncthreads();

    const uint32_t* Qu = (const uint32_t*)Qh;
    uint32_t* Su = (uint32_t*)Sh;
    const uint32_t qbase = smem_u32p(Qh);
    const uint32_t kbase = smem_u32p(Kh);
    const uint32_t sbase = smem_u32p(Sh);
    const int r0 = warp * 16;

    const uint32_t aRowQ = (uint32_t)((r0 + (g & 1) * 8 + rr) * 144 + (g >> 1) * 16);
    const uint32_t aRowS = (uint32_t)((r0 + (g & 1) * 8 + rr) * 272 + (g >> 1) * 16);
    const uint32_t bRowK = (uint32_t)(((g >> 1) * 8 + rr) * 144 + (g & 1) * 16);

    {
        float acc1[16][4];
#pragma unroll
        for (int nt = 0; nt < 16; nt++)
#pragma unroll
            for (int r = 0; r < 4; r++) acc1[nt][r] = 0.0f;

#pragma unroll
        for (int ks = 0; ks < 4; ks++) {
            uint32_t aq[4];
            LDMATRIX_X4(aq[0], aq[1], aq[2], aq[3], qbase + aRowQ + ks * 32);
#pragma unroll
            for (int p = 0; p < 8; p++) {
                uint32_t bk[4];
                LDMATRIX_X4(bk[0], bk[1], bk[2], bk[3],
                            kbase + bRowK + (uint32_t)(p * 16 * 144) + ks * 32);
                MMA_F16(acc1[2 * p],     aq[0], aq[1], aq[2], aq[3], bk[0], bk[1]);
                MMA_F16(acc1[2 * p + 1], aq[0], aq[1], aq[2], aq[3], bk[2], bk[3]);
            }
        }

        int row_lo = r0 + gid, row_hi = row_lo + 8;
        float sum_lo = 0.0f, sum_hi = 0.0f;
#pragma unroll
        for (int nt = 0; nt < 16; nt++) {
            int c0 = nt * 8 + tig * 2, c1 = c0 + 1;
            float v0 = (c0 <= row_lo) ? acc1[nt][0] : 0.0f;
            float v1 = (c1 <= row_lo) ? acc1[nt][1] : 0.0f;
            float v2 = (c0 <= row_hi) ? acc1[nt][2] : 0.0f;
            float v3 = (c1 <= row_hi) ? acc1[nt][3] : 0.0f;
            sum_lo += v0 + v1;
            sum_hi += v2 + v3;
            Su[row_lo * PSU + nt * 4 + tig] = h2_to_u32(__floats2half2_rn(v0, v1));
            Su[row_hi * PSU + nt * 4 + tig] = h2_to_u32(__floats2half2_rn(v2, v3));
        }
        sum_lo += __shfl_xor_sync(0xffffffff, sum_lo, 1);
        sum_lo += __shfl_xor_sync(0xffffffff, sum_lo, 2);
        sum_hi += __shfl_xor_sync(0xffffffff, sum_hi, 1);
        sum_hi += __shfl_xor_sync(0xffffffff, sum_hi, 2);
        if (tig == 0) { rowsum[row_lo] = sum_lo; rowsum[row_hi] = sum_hi; }
    }
    __syncthreads();

    if (tid < 128) {
        float dsum = rowsum[tid];
        const uint32_t* Qr = Qu + tid * PQU;
#pragma unroll
        for (int dd = 0; dd < 32; dd++) {
            float2 qv = __half22float2(u32_to_h2(Qr[dd]));
            dsum += qv.x * KSp[dd * 2] + qv.y * KSp[dd * 2 + 1];
        }
        den[tid] = 1.0f / fmaxf(dsum, 1e-6f);
    }
    __syncthreads();

    {
        float acc2[8][4];
#pragma unroll
        for (int nt = 0; nt < 8; nt++)
#pragma unroll
            for (int r = 0; r < 4; r++) acc2[nt][r] = 0.0f;

        const uint32_t vbase = smem_u32p(Vh);
        const uint32_t kvbase = smem_u32p(KVph);
        const int sel = lane >> 3;
        const int srow_in = ((sel & 1) << 3) + (lane & 7);
        const int ncol_in = (sel >> 1) << 3;

#pragma unroll
        for (int ks = 0; ks < 8; ks++) {
            uint32_t as[4];
            LDMATRIX_X4(as[0], as[1], as[2], as[3], sbase + aRowS + ks * 32);
#pragma unroll
            for (int nt2 = 0; nt2 < 4; nt2++) {
                uint32_t addr = vbase + (uint32_t)((ks * 16 + srow_in) * 144 + (nt2 * 16 + ncol_in) * 2);
                uint32_t b0, b1, b2, b3;
                LDMATRIX_X4_TRANS(b0, b1, b2, b3, addr);
                MMA_F16(acc2[nt2 * 2],     as[0], as[1], as[2], as[3], b0, b1);
                MMA_F16(acc2[nt2 * 2 + 1], as[0], as[1], as[2], as[3], b2, b3);
            }
        }
#pragma unroll
        for (int ks = 0; ks < 4; ks++) {
            uint32_t aq[4];
            LDMATRIX_X4(aq[0], aq[1], aq[2], aq[3], qbase + aRowQ + ks * 32);
#pragma unroll
            for (int nt2 = 0; nt2 < 4; nt2++) {
                uint32_t addr = kvbase + (uint32_t)((ks * 16 + srow_in) * 144 + (nt2 * 16 + ncol_in) * 2);
                uint32_t b0, b1, b2, b3;
                LDMATRIX_X4_TRANS(b0, b1, b2, b3, addr);
                MMA_F16(acc2[nt2 * 2],     aq[0], aq[1], aq[2], aq[3], b0, b1);
                MMA_F16(acc2[nt2 * 2 + 1], aq[0], aq[1], aq[2], aq[3], b2, b3);
            }
        }

        int row_lo = r0 + gid, row_hi = row_lo + 8;
        float inv_lo = den[row_lo], inv_hi = den[row_hi];
        size_t obL = ((size_t)b * SEQ + (size_t)c * CHUNK + row_lo) * DIM + h * 64;
        size_t obH = obL + (size_t)8 * DIM;
#pragma unroll
        for (int nt = 0; nt < 8; nt++) {
            int c0 = nt * 8 + tig * 2;
            *(__half2*)(attn + obL + c0) = __floats2half2_rn(acc2[nt][0] * inv_lo, acc2[nt][1] * inv_lo);
            *(__half2*)(attn + obH + c0) = __floats2half2_rn(acc2[nt][2] * inv_hi, acc2[nt][3] * inv_hi);
        }
    }
}

// ---------------- host launch ----------------
extern "C" void kernel_launch(void* const* d_in, const int* in_sizes, int n_in,
                              void* d_out, int out_size) {
    const float* x    = (const float*)d_in[0];
    const float* wqkv = (const float*)d_in[1];
    const float* wout = (const float*)d_in[2];
    float* out = (float*)d_out;

    float *kvch, *ksch;
    __half *xh, *wqkvT, *woutT, *qh, *kh, *vh, *attnh;
    cudaGetSymbolAddress((void**)&xh,    g_xh);
    cudaGetSymbolAddress((void**)&wqkvT, g_wqkvT);
    cudaGetSymbolAddress((void**)&woutT, g_woutT);
    cudaGetSymbolAddress((void**)&qh,    g_qh);
    cudaGetSymbolAddress((void**)&kh,    g_kh);
    cudaGetSymbolAddress((void**)&vh,    g_vh);
    cudaGetSymbolAddress((void**)&attnh, g_attnh);
    cudaGetSymbolAddress((void**)&kvch,  g_kvch);
    cudaGetSymbolAddress((void**)&ksch,  g_ksch);

    const size_t smemG  = 3 * STAGE_B;               // 61440 B
    const size_t smemGQ = 128 * 132 * sizeof(float); // 67584 B (covers pipeline too)
    const size_t smemS  = 2 * 18432;
    const size_t smemC  = 100608;
    cudaFuncSetAttribute(gemm_f16,      cudaFuncAttributeMaxDynamicSharedMemorySize, (int)smemG);
    cudaFuncSetAttribute(gemm_qkv,      cudaFuncAttributeMaxDynamicSharedMemorySize, (int)smemGQ);
    cudaFuncSetAttribute(chunk_sums_tc, cudaFuncAttributeMaxDynamicSharedMemorySize, (int)smemS);
    cudaFuncSetAttribute(chunk_out_tc,  cudaFuncAttributeMaxDynamicSharedMemorySize, (int)smemC);

    // 0) fp16 conversions
    {
        int n2x = (BATCH * SEQ * DIM) / 2;
        f32_to_f16_kernel<<<(n2x + 255) / 256, 256>>>((const float2*)x, (__half2*)xh, n2x);
        transpose_f16<<<dim3(3 * DIM / 32, DIM / 32), dim3(32, 8)>>>(wqkv, wqkvT, DIM, 3 * DIM);
        transpose_f16<<<dim3(DIM / 32, DIM / 32), dim3(32, 8)>>>(wout, woutT, DIM, DIM);
    }

    // 1) fused qkv GEMM + RoPE + ELU -> fp16 q/k/v in [bh][n][64]
    gemm_qkv<<<dim3(3072 / 128, 16384 / 128), 256, smemGQ>>>(xh, wqkvT, qh, kh, vh);
    // 2) per-chunk K^T V sums (tensor cores, fp32 out)
    chunk_sums_tc<<<BH * NCHUNK, 256, smemS>>>(kh, vh, kvch, ksch);
    // 3) exclusive prefix across chunks (batched loads)
    prefix_kernel<<<BH, 1024>>>(kvch, ksch);
    // 4) per-chunk outputs via tensor cores
    chunk_out_tc<<<BH * NCHUNK, 256, smemC>>>(qh, kh, vh, kvch, ksch, attnh);
    // 5) final = attnh @ woutT^T
    gemm_f16<<<dim3(1024 / 128, 16384 / 128), 256, smemG>>>(attnh, woutT, out, BATCH * SEQ, DIM, DIM);
}

// round 13
// speedup vs baseline: 1.1341x; 1.0006x over previous
#include <cuda_runtime.h>
#include <cuda_fp16.h>
#include <math.h>
#include <stdint.h>

#define BATCH 4
#define SEQ   4096
#define DIM   1024
#define HEADS 16
#define DH    64
#define CHUNK 128
#define NCHUNK 32
#define BH    (BATCH*HEADS)
#define FEAT_SCALE 0.35355339059327373f  // 64^-0.25

// ---------------- scratch (device globals; no allocation allowed) ----------------
__device__ __half g_xh   [BATCH*SEQ*DIM];     // fp16 x
__device__ __half g_wqkvT[3*DIM*DIM];         // K-major fp16
__device__ __half g_woutT[DIM*DIM];           // K-major fp16
__device__ __half g_qh  [BH*SEQ*DH];          // featurized q (fp16)
__device__ __half g_kh  [BH*SEQ*DH];          // featurized k (fp16)
__device__ __half g_vh  [BH*SEQ*DH];          // v (fp16)
__device__ __half g_attnh[BATCH*SEQ*DIM];     // attention out, fp16
__device__ float  g_kvch[BH*NCHUNK*DH*DH];
__device__ float  g_ksch[BH*NCHUNK*DH];
__device__ float2 g_rope[SEQ*32];             // (cos*SCALE, sin*SCALE) per (n, d)

// ---------------- helpers ----------------
__device__ __forceinline__ uint32_t h2_to_u32(__half2 h) {
    __half2_raw r = *(__half2_raw*)&h;
    return (uint32_t)r.x | ((uint32_t)r.y << 16);
}
__device__ __forceinline__ __half2 u32_to_h2(uint32_t u) {
    __half2_raw r;
    r.x = (unsigned short)(u & 0xFFFF);
    r.y = (unsigned short)(u >> 16);
    return *(__half2*)&r;
}
__device__ __forceinline__ void cpasync16(void* dst, const void* src) {
    unsigned d = (unsigned)__cvta_generic_to_shared(dst);
    asm volatile("cp.async.ca.shared.global [%0], [%1], 16;" :: "r"(d), "l"(src));
}
#define CP_COMMIT()  asm volatile("cp.async.commit_group;")
#define CP_WAIT1()   asm volatile("cp.async.wait_group 1;")

#define MMA_F16(acc, a0, a1, a2, a3, b0, b1) \
    asm volatile("mma.sync.aligned.m16n8k16.row.col.f32.f16.f16.f32 " \
        "{%0,%1,%2,%3}, {%4,%5,%6,%7}, {%8,%9}, {%0,%1,%2,%3};" \
        : "+f"((acc)[0]), "+f"((acc)[1]), "+f"((acc)[2]), "+f"((acc)[3]) \
        : "r"(a0), "r"(a1), "r"(a2), "r"(a3), "r"(b0), "r"(b1))

#define LDMATRIX_X4(r0, r1, r2, r3, addr) \
    asm volatile("ldmatrix.sync.aligned.m8n8.x4.shared.b16 {%0,%1,%2,%3}, [%4];" \
        : "=r"(r0), "=r"(r1), "=r"(r2), "=r"(r3) : "r"(addr))

#define LDMATRIX_X4_TRANS(r0, r1, r2, r3, addr) \
    asm volatile("ldmatrix.sync.aligned.m8n8.x4.trans.shared.b16 {%0,%1,%2,%3}, [%4];" \
        : "=r"(r0), "=r"(r1), "=r"(r2), "=r"(r3) : "r"(addr))

__device__ __forceinline__ uint32_t smem_u32p(const void* p) {
    return (uint32_t)__cvta_generic_to_shared(p);
}
__device__ __forceinline__ float exp_fast(float y) {   // exp(y), |err| ~2ulp
    float r;
    asm("ex2.approx.f32 %0, %1;" : "=f"(r) : "f"(y * 1.4426950408889634f));
    return r;
}

// fp32 sincos, FMA Cody-Waite range reduction (accurate ~1e-7 for ang < 5000)
__device__ __forceinline__ void rope_sincos_f(float ang, float& s, float& c) {
    float qf = rintf(ang * 0.63661977f);
    float r = fmaf(-qf, 1.57079637e+0f, ang);
    r = fmaf(qf, 4.37113900e-8f, r);
    int qi = (int)qf & 3;
    float r2 = r * r;
    float sp = r * (1.0f + r2 * (-1.6666667e-1f + r2 * (8.3333337e-3f
              + r2 * (-1.9841270e-4f + r2 * 2.7557319e-6f))));
    float cp = 1.0f + r2 * (-0.5f + r2 * (4.1666668e-2f
              + r2 * (-1.3888889e-3f + r2 * 2.4801587e-5f)));
    switch (qi) {
        case 0:  s =  sp; c =  cp; break;
        case 1:  s =  cp; c = -sp; break;
        case 2:  s = -sp; c = -cp; break;
        default: s = -cp; c =  sp; break;
    }
}

// ---------------- rope table: (cos*S, sin*S) for (n, d) ----------------
__global__ void rope_table_kernel(float2* __restrict__ tbl) {
    int idx = blockIdx.x * blockDim.x + threadIdx.x;   // SEQ*32 threads
    int d = idx & 31;
    int n = idx >> 5;
    float inv_f = (float)exp(-(double)d * (9.210340371976184 / 32.0));
    float ang = (float)n * inv_f;
    float s, c;
    rope_sincos_f(ang, s, c);
    tbl[idx] = make_float2(c * FEAT_SCALE, s * FEAT_SCALE);
}

// ---------------- fp16 conversion pre-passes ----------------
__global__ void f32_to_f16_kernel(const float2* __restrict__ in, __half2* __restrict__ out, int n2) {
    int i = blockIdx.x * blockDim.x + threadIdx.x;
    if (i < n2) out[i] = __float22half2_rn(in[i]);
}

__global__ void transpose_f16(const float* __restrict__ W, __half* __restrict__ WT,
                              int K, int Nn) {
    __shared__ float t[32][33];
    int n0 = blockIdx.x * 32, k0 = blockIdx.y * 32;
    int tx = threadIdx.x, ty = threadIdx.y;
#pragma unroll
    for (int i = 0; i < 32; i += 8)
        t[ty + i][tx] = W[(size_t)(k0 + ty + i) * Nn + n0 + tx];
    __syncthreads();
#pragma unroll
    for (int i = 0; i < 32; i += 8)
        WT[(size_t)(n0 + ty + i) * K + k0 + tx] = __float2half(t[tx][ty + i]);
}

// ---------------- generic fp16 GEMM (128x128, single sync/iter) ----------------
#define STAGE_B 20480      // bytes per stage: A 10240 + B 10240 (pitch 80 B)
__global__ __launch_bounds__(256) void gemm_f16(
        const __half* __restrict__ A, const __half* __restrict__ BT,
        float* __restrict__ C, int M, int Nn, int K) {
    extern __shared__ char smc[];
    const int tid = threadIdx.x;
    const int bx = blockIdx.x, by = blockIdx.y;
    const int warp = tid >> 5, lane = tid & 31;
    const int gid = lane >> 2, tig = lane & 3;
    const int g = lane >> 3, rr = lane & 7;
    const int warpM = warp & 1, warpN = warp >> 1;
    const int mBase = warpM * 64;
    const int nBase = warpN * 32;

    const __half* Ab = A  + (size_t)(by * 128) * K;
    const __half* Bb = BT + (size_t)(bx * 128) * K;
    const uint32_t smbase = smem_u32p(smc);

    float acc[4][4][4];
#pragma unroll
    for (int mi = 0; mi < 4; mi++)
#pragma unroll
        for (int nj = 0; nj < 4; nj++)
#pragma unroll
            for (int r = 0; r < 4; r++) acc[mi][nj][r] = 0.0f;

    const int KT = K >> 5;

    auto load_tile = [&](int kt, char* buf) {
        char* As = buf;
        char* Bs = buf + 10240;
        int k0 = kt * 32;
#pragma unroll
        for (int i = 0; i < 2; i++) {
            int c = i * 256 + tid;
            int m = c >> 2, k8 = (c & 3) * 8;
            cpasync16(As + m * 80 + k8 * 2, Ab + (size_t)m * K + k0 + k8);
        }
#pragma unroll
        for (int i = 0; i < 2; i++) {
            int c = i * 256 + tid;
            int n = c >> 2, k8 = (c & 3) * 8;
            cpasync16(Bs + n * 80 + k8 * 2, Bb + (size_t)n * K + k0 + k8);
        }
    };

    load_tile(0, smc);
    CP_COMMIT();
    load_tile(1, smc + STAGE_B);
    CP_COMMIT();

    const uint32_t aRow = (uint32_t)((mBase + (g & 1) * 8 + rr) * 80) + (uint32_t)((g >> 1) * 16);
    const uint32_t bRow = (uint32_t)((nBase + (g >> 1) * 8 + rr) * 80) + (uint32_t)((g & 1) * 16);

    for (int kt = 0; kt < KT; kt++) {
        CP_WAIT1();
        __syncthreads();
        if (kt + 2 < KT) load_tile(kt + 2, smc + ((kt + 2) % 3) * STAGE_B);
        CP_COMMIT();

        uint32_t ab = smbase + (uint32_t)((kt % 3) * STAGE_B);
        uint32_t bb = ab + 10240;

#pragma unroll
        for (int s = 0; s < 2; s++) {
            uint32_t af[4][4];
            uint32_t bq[2][4];
            uint32_t aoff = ab + aRow + s * 32;
            uint32_t boff = bb + bRow + s * 32;
#pragma unroll
            for (int mi = 0; mi < 4; mi++)
                LDMATRIX_X4(af[mi][0], af[mi][1], af[mi][2], af[mi][3], aoff + mi * (16 * 80));
#pragma unroll
            for (int p = 0; p < 2; p++)
                LDMATRIX_X4(bq[p][0], bq[p][1], bq[p][2], bq[p][3], boff + p * (16 * 80));
#pragma unroll
            for (int mi = 0; mi < 4; mi++)
#pragma unroll
                for (int nj = 0; nj < 4; nj++)
                    MMA_F16(acc[mi][nj], af[mi][0], af[mi][1], af[mi][2], af[mi][3],
                            bq[nj >> 1][(nj & 1) * 2], bq[nj >> 1][(nj & 1) * 2 + 1]);
        }
    }

#pragma unroll
    for (int mi = 0; mi < 4; mi++) {
        int row = by * 128 + mBase + mi * 16 + gid;
#pragma unroll
        for (int nj = 0; nj < 4; nj++) {
            int col = bx * 128 + nBase + nj * 8 + tig * 2;
            *(float2*)(C + (size_t)row * Nn + col)       = make_float2(acc[mi][nj][0], acc[mi][nj][1]);
            *(float2*)(C + (size_t)(row + 8) * Nn + col) = make_float2(acc[mi][nj][2], acc[mi][nj][3]);
        }
    }
}

// ---------------- fused QKV GEMM + RoPE(table) + ELU featurize ----------------
__global__ __launch_bounds__(256) void gemm_qkv(
        const __half* __restrict__ A, const __half* __restrict__ BT,
        const float2* __restrict__ rope,
        __half* __restrict__ qh, __half* __restrict__ kh, __half* __restrict__ vh) {
    extern __shared__ char smc[];
    const int K = DIM;
    const int tid = threadIdx.x;
    const int bx = blockIdx.x, by = blockIdx.y;
    const int warp = tid >> 5, lane = tid & 31;
    const int gid = lane >> 2, tig = lane & 3;
    const int g = lane >> 3, rr = lane & 7;
    const int warpM = warp & 1, warpN = warp >> 1;
    const int mBase = warpM * 64;
    const int nBase = warpN * 32;

    const __half* Ab = A + (size_t)(by * 128) * K;
    const __half* Bb = BT + (size_t)(bx * 128) * K;
    const uint32_t smbase = smem_u32p(smc);

    float acc[4][4][4];
#pragma unroll
    for (int mi = 0; mi < 4; mi++)
#pragma unroll
        for (int nj = 0; nj < 4; nj++)
#pragma unroll
            for (int r = 0; r < 4; r++) acc[mi][nj][r] = 0.0f;

    const int KT = K >> 5;

    auto load_tile = [&](int kt, char* buf) {
        char* As = buf;
        char* Bs = buf + 10240;
        int k0 = kt * 32;
#pragma unroll
        for (int i = 0; i < 2; i++) {
            int c = i * 256 + tid;
            int m = c >> 2, k8 = (c & 3) * 8;
            cpasync16(As + m * 80 + k8 * 2, Ab + (size_t)m * K + k0 + k8);
        }
#pragma unroll
        for (int i = 0; i < 2; i++) {
            int c = i * 256 + tid;
            int n = c >> 2, k8 = (c & 3) * 8;
            cpasync16(Bs + n * 80 + k8 * 2, Bb + (size_t)n * K + k0 + k8);
        }
    };

    load_tile(0, smc);
    CP_COMMIT();
    load_tile(1, smc + STAGE_B);
    CP_COMMIT();

    const uint32_t aRow = (uint32_t)((mBase + (g & 1) * 8 + rr) * 80) + (uint32_t)((g >> 1) * 16);
    const uint32_t bRow = (uint32_t)((nBase + (g >> 1) * 8 + rr) * 80) + (uint32_t)((g & 1) * 16);

    for (int kt = 0; kt < KT; kt++) {
        CP_WAIT1();
        __syncthreads();
        if (kt + 2 < KT) load_tile(kt + 2, smc + ((kt + 2) % 3) * STAGE_B);
        CP_COMMIT();

        uint32_t ab = smbase + (uint32_t)((kt % 3) * STAGE_B);
        uint32_t bb = ab + 10240;

#pragma unroll
        for (int s = 0; s < 2; s++) {
            uint32_t af[4][4];
            uint32_t bq[2][4];
            uint32_t aoff = ab + aRow + s * 32;
            uint32_t boff = bb + bRow + s * 32;
#pragma unroll
            for (int mi = 0; mi < 4; mi++)
                LDMATRIX_X4(af[mi][0], af[mi][1], af[mi][2], af[mi][3], aoff + mi * (16 * 80));
#pragma unroll
            for (int p = 0; p < 2; p++)
                LDMATRIX_X4(bq[p][0], bq[p][1], bq[p][2], bq[p][3], boff + p * (16 * 80));
#pragma unroll
            for (int mi = 0; mi < 4; mi++)
#pragma unroll
                for (int nj = 0; nj < 4; nj++)
                    MMA_F16(acc[mi][nj], af[mi][0], af[mi][1], af[mi][2], af[mi][3],
                            bq[nj >> 1][(nj & 1) * 2], bq[nj >> 1][(nj & 1) * 2 + 1]);
        }
    }

    // ---- epilogue: stage tile fp32, featurize via table, store fp16 ----
    __syncthreads();
    float* St = (float*)smc;         // 128 x pitch 132 floats
#pragma unroll
    for (int mi = 0; mi < 4; mi++) {
        int r = mBase + mi * 16 + gid;
#pragma unroll
        for (int nj = 0; nj < 4; nj++) {
            int ccol = nBase + nj * 8 + tig * 2;
            *(float2*)&St[r * 132 + ccol]       = make_float2(acc[mi][nj][0], acc[mi][nj][1]);
            *(float2*)&St[(r + 8) * 132 + ccol] = make_float2(acc[mi][nj][2], acc[mi][nj][3]);
        }
    }
    __syncthreads();

    const int sel   = bx >> 3;           // 0=q, 1=k, 2=v
    const int hbase = (bx & 7) * 2;
    const int d     = tid & 31;
    const int hh    = (tid >> 5) & 1;
    const int rbase = tid >> 6;          // 0..3
    const int bb    = by >> 5;           // batch
    const int n0    = (by * 128) & 4095;

    __half* dst = (sel == 0) ? qh : ((sel == 1) ? kh : vh);

#pragma unroll 4
    for (int k = 0; k < 32; k++) {
        int row = rbase + k * 4;
        float x1 = St[row * 132 + hh * 64 + d];
        float x2 = St[row * 132 + hh * 64 + d + 32];
        float f1, f2;
        if (sel == 2) {
            f1 = x1; f2 = x2;
        } else {
            float2 cs = rope[(n0 + row) * 32 + d];     // (c*S, s*S)
            float y1 = x1 * cs.x - x2 * cs.y;
            float y2 = x1 * cs.y + x2 * cs.x;
            f1 = (y1 > 0.0f) ? y1 + 1.0f : exp_fast(y1);
            f2 = (y2 > 0.0f) ? y2 + 1.0f : exp_fast(y2);
        }
        size_t ob = (((size_t)(bb * HEADS + hbase + hh)) * SEQ + (n0 + row)) * DH + d;
        dst[ob]      = __float2half(f1);
        dst[ob + 32] = __float2half(f2);
    }
}

// ---------------- pass A: tensor-core per-chunk K^T V (64x64) and sum(k) ----------------
__global__ __launch_bounds__(256) void chunk_sums_tc(
        const __half* __restrict__ kh, const __half* __restrict__ vh,
        float* __restrict__ kvch, float* __restrict__ ksch) {
    extern __shared__ char smem[];
    __half* Kh = (__half*)smem;              // 128 x 144 B = 18432
    __half* Vh = (__half*)(smem + 18432);    // 18432

    const int blk = blockIdx.x;
    const int c  = blk % NCHUNK;
    const int bh = blk / NCHUNK;
    const int tid = threadIdx.x;
    const int warp = tid >> 5, lane = tid & 31;
    const int gid = lane >> 2, tig = lane & 3;
    const int g = lane >> 3, rr = lane & 7;

    size_t gbase = (((size_t)bh) * SEQ + (size_t)c * CHUNK) * DH;
    for (int i = tid; i < 1024; i += 256) {
        int row = i >> 3, c16 = (i & 7) * 16;
        *(float4*)((char*)Kh + row * 144 + c16) = ((const float4*)(kh + gbase))[i];
        *(float4*)((char*)Vh + row * 144 + c16) = ((const float4*)(vh + gbase))[i];
    }
    __syncthreads();

    const uint32_t kbase = smem_u32p(Kh);
    const uint32_t vbase = smem_u32p(Vh);
    const int d0 = (warp & 3) * 16;
    const int m0 = (warp >> 2) * 32;

    float acc[4][4];
#pragma unroll
    for (int nt = 0; nt < 4; nt++)
#pragma unroll
        for (int r = 0; r < 4; r++) acc[nt][r] = 0.0f;

    const uint32_t aAddr = (uint32_t)(((g >> 1) * 8 + rr) * 144 + (d0 + (g & 1) * 8) * 2);
    const uint32_t bAddr = (uint32_t)(((g & 1) * 8 + rr) * 144 + (m0 + (g >> 1) * 8) * 2);

#pragma unroll
    for (int ks = 0; ks < 8; ks++) {
        uint32_t a0, a1, a2, a3;
        LDMATRIX_X4_TRANS(a0, a1, a2, a3, kbase + aAddr + (uint32_t)(ks * 16 * 144));
#pragma unroll
        for (int p = 0; p < 2; p++) {
            uint32_t b0, b1, b2, b3;
            LDMATRIX_X4_TRANS(b0, b1, b2, b3,
                              vbase + bAddr + (uint32_t)(ks * 16 * 144) + (uint32_t)(p * 32));
            MMA_F16(acc[p * 2],     a0, a1, a2, a3, b0, b1);
            MMA_F16(acc[p * 2 + 1], a0, a1, a2, a3, b2, b3);
        }
    }

    size_t obase = ((size_t)bh * NCHUNK + c) * (DH * DH);
    int row_lo = d0 + gid, row_hi = row_lo + 8;
#pragma unroll
    for (int nt = 0; nt < 4; nt++) {
        int col = m0 + nt * 8 + tig * 2;
        *(float2*)&kvch[obase + (size_t)row_lo * 64 + col] = make_float2(acc[nt][0], acc[nt][1]);
        *(float2*)&kvch[obase + (size_t)row_hi * 64 + col] = make_float2(acc[nt][2], acc[nt][3]);
    }

    if (tid < 64) {
        float ssum = 0.0f;
        for (int r = 0; r < 128; r++)
            ssum += __half2float(Kh[r * 72 + tid]);
        ksch[((size_t)bh * NCHUNK + c) * DH + tid] = ssum;
    }
}

// ---------------- pass B: exclusive prefix over chunks (batched loads) ----------------
__global__ void prefix_kernel(float* __restrict__ kvch, float* __restrict__ ksch) {
    int bh = blockIdx.x;
    for (int e = threadIdx.x; e < DH * DH; e += blockDim.x) {
        float* p = &kvch[(size_t)bh * NCHUNK * (DH * DH) + e];
        float r[NCHUNK];
#pragma unroll
        for (int c = 0; c < NCHUNK; c++) r[c] = p[(size_t)c * (DH * DH)];
        float acc = 0.0f;
#pragma unroll
        for (int c = 0; c < NCHUNK; c++) {
            float t = r[c];
            p[(size_t)c * (DH * DH)] = acc;
            acc += t;
        }
    }
    if (threadIdx.x < DH) {
        float* p = &ksch[(size_t)bh * NCHUNK * DH + threadIdx.x];
        float r[NCHUNK];
#pragma unroll
        for (int c = 0; c < NCHUNK; c++) r[c] = p[(size_t)c * DH];
        float acc = 0.0f;
#pragma unroll
        for (int c = 0; c < NCHUNK; c++) {
            float t = r[c];
            p[(size_t)c * DH] = acc;
            acc += t;
        }
    }
}

// ---------------- pass C: tensor-core per-chunk output ----------------
#define PQU 36
#define PSU 68
__global__ __launch_bounds__(256) void chunk_out_tc(
        const __half* __restrict__ qh, const __half* __restrict__ kh,
        const __half* __restrict__ vh, const float* __restrict__ kvch,
        const float* __restrict__ ksch, __half* __restrict__ attn) {
    extern __shared__ char smem[];
    __half* Qh   = (__half*)smem;
    __half* Kh   = (__half*)(smem + 18432);
    __half* Vh   = (__half*)(smem + 36864);
    __half* KVph = (__half*)(smem + 55296);
    __half* Sh   = (__half*)(smem + 64512);
    float* rowsum = (float*)(smem + 99328);
    float* den    = (float*)(smem + 99840);
    float* KSp    = (float*)(smem + 100352);

    const int blk = blockIdx.x;
    const int c  = blk % NCHUNK;
    const int bh = blk / NCHUNK;
    const int b  = bh / HEADS;
    const int h  = bh % HEADS;
    const int tid = threadIdx.x;
    const int warp = tid >> 5, lane = tid & 31;
    const int gid = lane >> 2, tig = lane & 3;
    const int g = lane >> 3, rr = lane & 7;

    size_t gbase = (((size_t)bh) * SEQ + (size_t)c * CHUNK) * DH;
    for (int i = tid; i < 1024; i += 256) {
        int row = i >> 3, c16 = (i & 7) * 16;
        *(float4*)((char*)Qh + row * 144 + c16) = ((const float4*)(qh + gbase))[i];
        *(float4*)((char*)Kh + row * 144 + c16) = ((const float4*)(kh + gbase))[i];
        *(float4*)((char*)Vh + row * 144 + c16) = ((const float4*)(vh + gbase))[i];
    }
    {
        size_t kvbase = ((size_t)bh * NCHUNK + c) * (DH * DH);
        for (int i = tid; i < 2048; i += 256) {
            int d = i >> 5, m2 = i & 31;
            float2 f = ((const float2*)(kvch + kvbase))[i];
            *(uint32_t*)((char*)KVph + d * 144 + m2 * 4) =
                h2_to_u32(__floats2half2_rn(f.x, f.y));
        }
        if (tid < 64)
            KSp[tid] = ksch[((size_t)bh * NCHUNK + c) * DH + tid];
    }
    __syncthreads();

    const uint32_t* Qu = (const uint32_t*)Qh;
    uint32_t* Su = (uint32_t*)Sh;
    const uint32_t qbase = smem_u32p(Qh);
    const uint32_t kbase = smem_u32p(Kh);
    const uint32_t sbase = smem_u32p(Sh);
    const int r0 = warp * 16;

    const uint32_t aRowQ = (uint32_t)((r0 + (g & 1) * 8 + rr) * 144 + (g >> 1) * 16);
    const uint32_t aRowS = (uint32_t)((r0 + (g & 1) * 8 + rr) * 272 + (g >> 1) * 16);
    const uint32_t bRowK = (uint32_t)(((g >> 1) * 8 + rr) * 144 + (g & 1) * 16);

    {
        float acc1[16][4];
#pragma unroll
        for (int nt = 0; nt < 16; nt++)
#pragma unroll
            for (int r = 0; r < 4; r++) acc1[nt][r] = 0.0f;

#pragma unroll
        for (int ks = 0; ks < 4; ks++) {
            uint32_t aq[4];
            LDMATRIX_X4(aq[0], aq[1], aq[2], aq[3], qbase + aRowQ + ks * 32);
#pragma unroll
            for (int p = 0; p < 8; p++) {
                uint32_t bk[4];
                LDMATRIX_X4(bk[0], bk[1], bk[2], bk[3],
                            kbase + bRowK + (uint32_t)(p * 16 * 144) + ks * 32);
                MMA_F16(acc1[2 * p],     aq[0], aq[1], aq[2], aq[3], bk[0], bk[1]);
                MMA_F16(acc1[2 * p + 1], aq[0], aq[1], aq[2], aq[3], bk[2], bk[3]);
            }
        }

        int row_lo = r0 + gid, row_hi = row_lo + 8;
        float sum_lo = 0.0f, sum_hi = 0.0f;
#pragma unroll
        for (int nt = 0; nt < 16; nt++) {
            int c0 = nt * 8 + tig * 2, c1 = c0 + 1;
            float v0 = (c0 <= row_lo) ? acc1[nt][0] : 0.0f;
            float v1 = (c1 <= row_lo) ? acc1[nt][1] : 0.0f;
            float v2 = (c0 <= row_hi) ? acc1[nt][2] : 0.0f;
            float v3 = (c1 <= row_hi) ? acc1[nt][3] : 0.0f;
            sum_lo += v0 + v1;
            sum_hi += v2 + v3;
            Su[row_lo * PSU + nt * 4 + tig] = h2_to_u32(__floats2half2_rn(v0, v1));
            Su[row_hi * PSU + nt * 4 + tig] = h2_to_u32(__floats2half2_rn(v2, v3));
        }
        sum_lo += __shfl_xor_sync(0xffffffff, sum_lo, 1);
        sum_lo += __shfl_xor_sync(0xffffffff, sum_lo, 2);
        sum_hi += __shfl_xor_sync(0xffffffff, sum_hi, 1);
        sum_hi += __shfl_xor_sync(0xffffffff, sum_hi, 2);
        if (tig == 0) { rowsum[row_lo] = sum_lo; rowsum[row_hi] = sum_hi; }
    }
    __syncthreads();

    if (tid < 128) {
        float dsum = rowsum[tid];
        const uint32_t* Qr = Qu + tid * PQU;
#pragma unroll
        for (int dd = 0; dd < 32; dd++) {
            float2 qv = __half22float2(u32_to_h2(Qr[dd]));
            dsum += qv.x * KSp[dd * 2] + qv.y * KSp[dd * 2 + 1];
        }
        den[tid] = 1.0f / fmaxf(dsum, 1e-6f);
    }
    __syncthreads();

    {
        float acc2[8][4];
#pragma unroll
        for (int nt = 0; nt < 8; nt++)
#pragma unroll
            for (int r = 0; r < 4; r++) acc2[nt][r] = 0.0f;

        const uint32_t vbase = smem_u32p(Vh);
        const uint32_t kvbase = smem_u32p(KVph);
        const int sel = lane >> 3;
        const int srow_in = ((sel & 1) << 3) + (lane & 7);
        const int ncol_in = (sel >> 1) << 3;

#pragma unroll
        for (int ks = 0; ks < 8; ks++) {
            uint32_t as[4];
            LDMATRIX_X4(as[0], as[1], as[2], as[3], sbase + aRowS + ks * 32);
#pragma unroll
            for (int nt2 = 0; nt2 < 4; nt2++) {
                uint32_t addr = vbase + (uint32_t)((ks * 16 + srow_in) * 144 + (nt2 * 16 + ncol_in) * 2);
                uint32_t b0, b1, b2, b3;
                LDMATRIX_X4_TRANS(b0, b1, b2, b3, addr);
                MMA_F16(acc2[nt2 * 2],     as[0], as[1], as[2], as[3], b0, b1);
                MMA_F16(acc2[nt2 * 2 + 1], as[0], as[1], as[2], as[3], b2, b3);
            }
        }
#pragma unroll
        for (int ks = 0; ks < 4; ks++) {
            uint32_t aq[4];
            LDMATRIX_X4(aq[0], aq[1], aq[2], aq[3], qbase + aRowQ + ks * 32);
#pragma unroll
            for (int nt2 = 0; nt2 < 4; nt2++) {
                uint32_t addr = kvbase + (uint32_t)((ks * 16 + srow_in) * 144 + (nt2 * 16 + ncol_in) * 2);
                uint32_t b0, b1, b2, b3;
                LDMATRIX_X4_TRANS(b0, b1, b2, b3, addr);
                MMA_F16(acc2[nt2 * 2],     aq[0], aq[1], aq[2], aq[3], b0, b1);
                MMA_F16(acc2[nt2 * 2 + 1], aq[0], aq[1], aq[2], aq[3], b2, b3);
            }
        }

        int row_lo = r0 + gid, row_hi = row_lo + 8;
        float inv_lo = den[row_lo], inv_hi = den[row_hi];
        size_t obL = ((size_t)b * SEQ + (size_t)c * CHUNK + row_lo) * DIM + h * 64;
        size_t obH = obL + (size_t)8 * DIM;
#pragma unroll
        for (int nt = 0; nt < 8; nt++) {
            int c0 = nt * 8 + tig * 2;
            *(__half2*)(attn + obL + c0) = __floats2half2_rn(acc2[nt][0] * inv_lo, acc2[nt][1] * inv_lo);
            *(__half2*)(attn + obH + c0) = __floats2half2_rn(acc2[nt][2] * inv_hi, acc2[nt][3] * inv_hi);
        }
    }
}

// ---------------- host launch ----------------
extern "C" void kernel_launch(void* const* d_in, const int* in_sizes, int n_in,
                              void* d_out, int out_size) {
    const float* x    = (const float*)d_in[0];
    const float* wqkv = (const float*)d_in[1];
    const float* wout = (const float*)d_in[2];
    float* out = (float*)d_out;

    float *kvch, *ksch;
    float2* rope;
    __half *xh, *wqkvT, *woutT, *qh, *kh, *vh, *attnh;
    cudaGetSymbolAddress((void**)&xh,    g_xh);
    cudaGetSymbolAddress((void**)&wqkvT, g_wqkvT);
    cudaGetSymbolAddress((void**)&woutT, g_woutT);
    cudaGetSymbolAddress((void**)&qh,    g_qh);
    cudaGetSymbolAddress((void**)&kh,    g_kh);
    cudaGetSymbolAddress((void**)&vh,    g_vh);
    cudaGetSymbolAddress((void**)&attnh, g_attnh);
    cudaGetSymbolAddress((void**)&kvch,  g_kvch);
    cudaGetSymbolAddress((void**)&ksch,  g_ksch);
    cudaGetSymbolAddress((void**)&rope,  g_rope);

    const size_t smemG  = 3 * STAGE_B;               // 61440 B
    const size_t smemGQ = 128 * 132 * sizeof(float); // 67584 B (covers pipeline too)
    const size_t smemS  = 2 * 18432;
    const size_t smemC  = 100608;
    cudaFuncSetAttribute(gemm_f16,      cudaFuncAttributeMaxDynamicSharedMemorySize, (int)smemG);
    cudaFuncSetAttribute(gemm_qkv,      cudaFuncAttributeMaxDynamicSharedMemorySize, (int)smemGQ);
    cudaFuncSetAttribute(chunk_sums_tc, cudaFuncAttributeMaxDynamicSharedMemorySize, (int)smemS);
    cudaFuncSetAttribute(chunk_out_tc,  cudaFuncAttributeMaxDynamicSharedMemorySize, (int)smemC);

    // 0) rope table + fp16 conversions
    {
        rope_table_kernel<<<(SEQ * 32) / 256, 256>>>(rope);
        int n2x = (BATCH * SEQ * DIM) / 2;
        f32_to_f16_kernel<<<(n2x + 255) / 256, 256>>>((const float2*)x, (__half2*)xh, n2x);
        transpose_f16<<<dim3(3 * DIM / 32, DIM / 32), dim3(32, 8)>>>(wqkv, wqkvT, DIM, 3 * DIM);
        transpose_f16<<<dim3(DIM / 32, DIM / 32), dim3(32, 8)>>>(wout, woutT, DIM, DIM);
    }

    // 1) fused qkv GEMM + RoPE(table) + ELU -> fp16 q/k/v in [bh][n][64]
    gemm_qkv<<<dim3(3072 / 128, 16384 / 128), 256, smemGQ>>>(xh, wqkvT, rope, qh, kh, vh);
    // 2) per-chunk K^T V sums (tensor cores, fp32 out)
    chunk_sums_tc<<<BH * NCHUNK, 256, smemS>>>(kh, vh, kvch, ksch);
    // 3) exclusive prefix across chunks
    prefix_kernel<<<BH, 1024>>>(kvch, ksch);
    // 4) per-chunk outputs via tensor cores
    chunk_out_tc<<<BH * NCHUNK, 256, smemC>>>(qh, kh, vh, kvch, ksch, attnh);
    // 5) final = attnh @ woutT^T
    gemm_f16<<<dim3(1024 / 128, 16384 / 128), 256, smemG>>>(attnh, woutT, out, BATCH * SEQ, DIM, DIM);
}

// round 14
// speedup vs baseline: 1.1439x; 1.0086x over previous
#include <cuda_runtime.h>
#include <cuda_fp16.h>
#include <math.h>
#include <stdint.h>

#define BATCH 4
#define SEQ   4096
#define DIM   1024
#define HEADS 16
#define DH    64
#define CHUNK 128
#define NCHUNK 32
#define BH    (BATCH*HEADS)
#define FEAT_SCALE 0.35355339059327373f  // 64^-0.25

// ---------------- scratch (device globals; no allocation allowed) ----------------
__device__ __half g_xh   [BATCH*SEQ*DIM];     // fp16 x
__device__ __half g_wqkvT[3*DIM*DIM];         // K-major fp16
__device__ __half g_woutT[DIM*DIM];           // K-major fp16
__device__ __half g_qh  [BH*SEQ*DH];          // featurized q (fp16)
__device__ __half g_kh  [BH*SEQ*DH];          // featurized k (fp16)
__device__ __half g_vh  [BH*SEQ*DH];          // v (fp16)
__device__ __half g_attnh[BATCH*SEQ*DIM];     // attention out, fp16
__device__ float  g_kvch[BH*NCHUNK*DH*DH];
__device__ float  g_ksch[BH*NCHUNK*DH];
__device__ float2 g_rope[SEQ*32];             // (cos*SCALE, sin*SCALE) per (n, d)

// ---------------- helpers ----------------
__device__ __forceinline__ uint32_t h2_to_u32(__half2 h) {
    __half2_raw r = *(__half2_raw*)&h;
    return (uint32_t)r.x | ((uint32_t)r.y << 16);
}
__device__ __forceinline__ __half2 u32_to_h2(uint32_t u) {
    __half2_raw r;
    r.x = (unsigned short)(u & 0xFFFF);
    r.y = (unsigned short)(u >> 16);
    return *(__half2*)&r;
}
__device__ __forceinline__ void cpasync16(void* dst, const void* src) {
    unsigned d = (unsigned)__cvta_generic_to_shared(dst);
    asm volatile("cp.async.ca.shared.global [%0], [%1], 16;" :: "r"(d), "l"(src));
}
#define CP_COMMIT()  asm volatile("cp.async.commit_group;")
#define CP_WAIT1()   asm volatile("cp.async.wait_group 1;")

#define MMA_F16(acc, a0, a1, a2, a3, b0, b1) \
    asm volatile("mma.sync.aligned.m16n8k16.row.col.f32.f16.f16.f32 " \
        "{%0,%1,%2,%3}, {%4,%5,%6,%7}, {%8,%9}, {%0,%1,%2,%3};" \
        : "+f"((acc)[0]), "+f"((acc)[1]), "+f"((acc)[2]), "+f"((acc)[3]) \
        : "r"(a0), "r"(a1), "r"(a2), "r"(a3), "r"(b0), "r"(b1))

#define LDMATRIX_X4(r0, r1, r2, r3, addr) \
    asm volatile("ldmatrix.sync.aligned.m8n8.x4.shared.b16 {%0,%1,%2,%3}, [%4];" \
        : "=r"(r0), "=r"(r1), "=r"(r2), "=r"(r3) : "r"(addr))

#define LDMATRIX_X4_TRANS(r0, r1, r2, r3, addr) \
    asm volatile("ldmatrix.sync.aligned.m8n8.x4.trans.shared.b16 {%0,%1,%2,%3}, [%4];" \
        : "=r"(r0), "=r"(r1), "=r"(r2), "=r"(r3) : "r"(addr))

__device__ __forceinline__ uint32_t smem_u32p(const void* p) {
    return (uint32_t)__cvta_generic_to_shared(p);
}
__device__ __forceinline__ float exp_fast(float y) {   // exp(y), |err| ~2ulp
    float r;
    asm("ex2.approx.f32 %0, %1;" : "=f"(r) : "f"(y * 1.4426950408889634f));
    return r;
}

// fp32 sincos, FMA Cody-Waite range reduction (accurate ~1e-7 for ang < 5000)
__device__ __forceinline__ void rope_sincos_f(float ang, float& s, float& c) {
    float qf = rintf(ang * 0.63661977f);
    float r = fmaf(-qf, 1.57079637e+0f, ang);
    r = fmaf(qf, 4.37113900e-8f, r);
    int qi = (int)qf & 3;
    float r2 = r * r;
    float sp = r * (1.0f + r2 * (-1.6666667e-1f + r2 * (8.3333337e-3f
              + r2 * (-1.9841270e-4f + r2 * 2.7557319e-6f))));
    float cp = 1.0f + r2 * (-0.5f + r2 * (4.1666668e-2f
              + r2 * (-1.3888889e-3f + r2 * 2.4801587e-5f)));
    switch (qi) {
        case 0:  s =  sp; c =  cp; break;
        case 1:  s =  cp; c = -sp; break;
        case 2:  s = -sp; c = -cp; break;
        default: s = -cp; c =  sp; break;
    }
}

// ---------------- prep: x->fp16 conversion + rope table (one launch) ----------------
#define N2X ((BATCH*SEQ*DIM)/2)
__global__ void prep_kernel(const float2* __restrict__ in, __half2* __restrict__ out,
                            float2* __restrict__ tbl) {
    int i = blockIdx.x * blockDim.x + threadIdx.x;
    if (i < N2X) {
        out[i] = __float22half2_rn(in[i]);
    } else {
        int idx = i - N2X;                     // SEQ*32 entries
        int d = idx & 31;
        int n = idx >> 5;
        float inv_f = (float)exp(-(double)d * (9.210340371976184 / 32.0));
        float ang = (float)n * inv_f;
        float s, c;
        rope_sincos_f(ang, s, c);
        tbl[idx] = make_float2(c * FEAT_SCALE, s * FEAT_SCALE);
    }
}

__global__ void transpose_f16(const float* __restrict__ W, __half* __restrict__ WT,
                              int K, int Nn) {
    __shared__ float t[32][33];
    int n0 = blockIdx.x * 32, k0 = blockIdx.y * 32;
    int tx = threadIdx.x, ty = threadIdx.y;
#pragma unroll
    for (int i = 0; i < 32; i += 8)
        t[ty + i][tx] = W[(size_t)(k0 + ty + i) * Nn + n0 + tx];
    __syncthreads();
#pragma unroll
    for (int i = 0; i < 32; i += 8)
        WT[(size_t)(n0 + ty + i) * K + k0 + tx] = __float2half(t[tx][ty + i]);
}

// ---------------- generic fp16 GEMM (128x128, single sync/iter) ----------------
#define STAGE_B 20480      // bytes per stage: A 10240 + B 10240 (pitch 80 B)
__global__ __launch_bounds__(256) void gemm_f16(
        const __half* __restrict__ A, const __half* __restrict__ BT,
        float* __restrict__ C, int M, int Nn, int K) {
    extern __shared__ char smc[];
    const int tid = threadIdx.x;
    const int bx = blockIdx.x, by = blockIdx.y;
    const int warp = tid >> 5, lane = tid & 31;
    const int gid = lane >> 2, tig = lane & 3;
    const int g = lane >> 3, rr = lane & 7;
    const int warpM = warp & 1, warpN = warp >> 1;
    const int mBase = warpM * 64;
    const int nBase = warpN * 32;

    const __half* Ab = A  + (size_t)(by * 128) * K;
    const __half* Bb = BT + (size_t)(bx * 128) * K;
    const uint32_t smbase = smem_u32p(smc);

    float acc[4][4][4];
#pragma unroll
    for (int mi = 0; mi < 4; mi++)
#pragma unroll
        for (int nj = 0; nj < 4; nj++)
#pragma unroll
            for (int r = 0; r < 4; r++) acc[mi][nj][r] = 0.0f;

    const int KT = K >> 5;

    auto load_tile = [&](int kt, char* buf) {
        char* As = buf;
        char* Bs = buf + 10240;
        int k0 = kt * 32;
#pragma unroll
        for (int i = 0; i < 2; i++) {
            int c = i * 256 + tid;
            int m = c >> 2, k8 = (c & 3) * 8;
            cpasync16(As + m * 80 + k8 * 2, Ab + (size_t)m * K + k0 + k8);
        }
#pragma unroll
        for (int i = 0; i < 2; i++) {
            int c = i * 256 + tid;
            int n = c >> 2, k8 = (c & 3) * 8;
            cpasync16(Bs + n * 80 + k8 * 2, Bb + (size_t)n * K + k0 + k8);
        }
    };

    load_tile(0, smc);
    CP_COMMIT();
    load_tile(1, smc + STAGE_B);
    CP_COMMIT();

    const uint32_t aRow = (uint32_t)((mBase + (g & 1) * 8 + rr) * 80) + (uint32_t)((g >> 1) * 16);
    const uint32_t bRow = (uint32_t)((nBase + (g >> 1) * 8 + rr) * 80) + (uint32_t)((g & 1) * 16);

    for (int kt = 0; kt < KT; kt++) {
        CP_WAIT1();
        __syncthreads();
        if (kt + 2 < KT) load_tile(kt + 2, smc + ((kt + 2) % 3) * STAGE_B);
        CP_COMMIT();

        uint32_t ab = smbase + (uint32_t)((kt % 3) * STAGE_B);
        uint32_t bb = ab + 10240;

#pragma unroll
        for (int s = 0; s < 2; s++) {
            uint32_t af[4][4];
            uint32_t bq[2][4];
            uint32_t aoff = ab + aRow + s * 32;
            uint32_t boff = bb + bRow + s * 32;
#pragma unroll
            for (int mi = 0; mi < 4; mi++)
                LDMATRIX_X4(af[mi][0], af[mi][1], af[mi][2], af[mi][3], aoff + mi * (16 * 80));
#pragma unroll
            for (int p = 0; p < 2; p++)
                LDMATRIX_X4(bq[p][0], bq[p][1], bq[p][2], bq[p][3], boff + p * (16 * 80));
#pragma unroll
            for (int mi = 0; mi < 4; mi++)
#pragma unroll
                for (int nj = 0; nj < 4; nj++)
                    MMA_F16(acc[mi][nj], af[mi][0], af[mi][1], af[mi][2], af[mi][3],
                            bq[nj >> 1][(nj & 1) * 2], bq[nj >> 1][(nj & 1) * 2 + 1]);
        }
    }

#pragma unroll
    for (int mi = 0; mi < 4; mi++) {
        int row = by * 128 + mBase + mi * 16 + gid;
#pragma unroll
        for (int nj = 0; nj < 4; nj++) {
            int col = bx * 128 + nBase + nj * 8 + tig * 2;
            *(float2*)(C + (size_t)row * Nn + col)       = make_float2(acc[mi][nj][0], acc[mi][nj][1]);
            *(float2*)(C + (size_t)(row + 8) * Nn + col) = make_float2(acc[mi][nj][2], acc[mi][nj][3]);
        }
    }
}

// ---------------- fused QKV GEMM + RoPE(table) + ELU featurize ----------------
__global__ __launch_bounds__(256) void gemm_qkv(
        const __half* __restrict__ A, const __half* __restrict__ BT,
        const float2* __restrict__ rope,
        __half* __restrict__ qh, __half* __restrict__ kh, __half* __restrict__ vh) {
    extern __shared__ char smc[];
    const int K = DIM;
    const int tid = threadIdx.x;
    const int bx = blockIdx.x, by = blockIdx.y;
    const int warp = tid >> 5, lane = tid & 31;
    const int gid = lane >> 2, tig = lane & 3;
    const int g = lane >> 3, rr = lane & 7;
    const int warpM = warp & 1, warpN = warp >> 1;
    const int mBase = warpM * 64;
    const int nBase = warpN * 32;

    const __half* Ab = A + (size_t)(by * 128) * K;
    const __half* Bb = BT + (size_t)(bx * 128) * K;
    const uint32_t smbase = smem_u32p(smc);

    float acc[4][4][4];
#pragma unroll
    for (int mi = 0; mi < 4; mi++)
#pragma unroll
        for (int nj = 0; nj < 4; nj++)
#pragma unroll
            for (int r = 0; r < 4; r++) acc[mi][nj][r] = 0.0f;

    const int KT = K >> 5;

    auto load_tile = [&](int kt, char* buf) {
        char* As = buf;
        char* Bs = buf + 10240;
        int k0 = kt * 32;
#pragma unroll
        for (int i = 0; i < 2; i++) {
            int c = i * 256 + tid;
            int m = c >> 2, k8 = (c & 3) * 8;
            cpasync16(As + m * 80 + k8 * 2, Ab + (size_t)m * K + k0 + k8);
        }
#pragma unroll
        for (int i = 0; i < 2; i++) {
            int c = i * 256 + tid;
            int n = c >> 2, k8 = (c & 3) * 8;
            cpasync16(Bs + n * 80 + k8 * 2, Bb + (size_t)n * K + k0 + k8);
        }
    };

    load_tile(0, smc);
    CP_COMMIT();
    load_tile(1, smc + STAGE_B);
    CP_COMMIT();

    const uint32_t aRow = (uint32_t)((mBase + (g & 1) * 8 + rr) * 80) + (uint32_t)((g >> 1) * 16);
    const uint32_t bRow = (uint32_t)((nBase + (g >> 1) * 8 + rr) * 80) + (uint32_t)((g & 1) * 16);

    for (int kt = 0; kt < KT; kt++) {
        CP_WAIT1();
        __syncthreads();
        if (kt + 2 < KT) load_tile(kt + 2, smc + ((kt + 2) % 3) * STAGE_B);
        CP_COMMIT();

        uint32_t ab = smbase + (uint32_t)((kt % 3) * STAGE_B);
        uint32_t bb = ab + 10240;

#pragma unroll
        for (int s = 0; s < 2; s++) {
            uint32_t af[4][4];
            uint32_t bq[2][4];
            uint32_t aoff = ab + aRow + s * 32;
            uint32_t boff = bb + bRow + s * 32;
#pragma unroll
            for (int mi = 0; mi < 4; mi++)
                LDMATRIX_X4(af[mi][0], af[mi][1], af[mi][2], af[mi][3], aoff + mi * (16 * 80));
#pragma unroll
            for (int p = 0; p < 2; p++)
                LDMATRIX_X4(bq[p][0], bq[p][1], bq[p][2], bq[p][3], boff + p * (16 * 80));
#pragma unroll
            for (int mi = 0; mi < 4; mi++)
#pragma unroll
                for (int nj = 0; nj < 4; nj++)
                    MMA_F16(acc[mi][nj], af[mi][0], af[mi][1], af[mi][2], af[mi][3],
                            bq[nj >> 1][(nj & 1) * 2], bq[nj >> 1][(nj & 1) * 2 + 1]);
        }
    }

    // ---- epilogue: stage tile fp32, featurize via table, store fp16 ----
    __syncthreads();
    float* St = (float*)smc;         // 128 x pitch 132 floats
#pragma unroll
    for (int mi = 0; mi < 4; mi++) {
        int r = mBase + mi * 16 + gid;
#pragma unroll
        for (int nj = 0; nj < 4; nj++) {
            int ccol = nBase + nj * 8 + tig * 2;
            *(float2*)&St[r * 132 + ccol]       = make_float2(acc[mi][nj][0], acc[mi][nj][1]);
            *(float2*)&St[(r + 8) * 132 + ccol] = make_float2(acc[mi][nj][2], acc[mi][nj][3]);
        }
    }
    __syncthreads();

    const int sel   = bx >> 3;           // 0=q, 1=k, 2=v
    const int hbase = (bx & 7) * 2;
    const int d     = tid & 31;
    const int hh    = (tid >> 5) & 1;
    const int rbase = tid >> 6;          // 0..3
    const int bb    = by >> 5;           // batch
    const int n0    = (by * 128) & 4095;

    __half* dst = (sel == 0) ? qh : ((sel == 1) ? kh : vh);

#pragma unroll 4
    for (int k = 0; k < 32; k++) {
        int row = rbase + k * 4;
        float x1 = St[row * 132 + hh * 64 + d];
        float x2 = St[row * 132 + hh * 64 + d + 32];
        float f1, f2;
        if (sel == 2) {
            f1 = x1; f2 = x2;
        } else {
            float2 cs = rope[(n0 + row) * 32 + d];     // (c*S, s*S)
            float y1 = x1 * cs.x - x2 * cs.y;
            float y2 = x1 * cs.y + x2 * cs.x;
            f1 = (y1 > 0.0f) ? y1 + 1.0f : exp_fast(y1);
            f2 = (y2 > 0.0f) ? y2 + 1.0f : exp_fast(y2);
        }
        size_t ob = (((size_t)(bb * HEADS + hbase + hh)) * SEQ + (n0 + row)) * DH + d;
        dst[ob]      = __float2half(f1);
        dst[ob + 32] = __float2half(f2);
    }
}

// ---------------- pass A: tensor-core per-chunk K^T V (64x64) and sum(k) ----------------
__global__ __launch_bounds__(256) void chunk_sums_tc(
        const __half* __restrict__ kh, const __half* __restrict__ vh,
        float* __restrict__ kvch, float* __restrict__ ksch) {
    extern __shared__ char smem[];
    __half* Kh = (__half*)smem;              // 128 x 144 B = 18432
    __half* Vh = (__half*)(smem + 18432);    // 18432
    float* red = (float*)(smem + 36864);     // [4][64] = 1024 B

    const int blk = blockIdx.x;
    const int c  = blk % NCHUNK;
    const int bh = blk / NCHUNK;
    const int tid = threadIdx.x;
    const int warp = tid >> 5, lane = tid & 31;
    const int gid = lane >> 2, tig = lane & 3;
    const int g = lane >> 3, rr = lane & 7;

    size_t gbase = (((size_t)bh) * SEQ + (size_t)c * CHUNK) * DH;
    for (int i = tid; i < 1024; i += 256) {
        int row = i >> 3, c16 = (i & 7) * 16;
        *(float4*)((char*)Kh + row * 144 + c16) = ((const float4*)(kh + gbase))[i];
        *(float4*)((char*)Vh + row * 144 + c16) = ((const float4*)(vh + gbase))[i];
    }
    __syncthreads();

    const uint32_t kbase = smem_u32p(Kh);
    const uint32_t vbase = smem_u32p(Vh);
    const int d0 = (warp & 3) * 16;
    const int m0 = (warp >> 2) * 32;

    float acc[4][4];
#pragma unroll
    for (int nt = 0; nt < 4; nt++)
#pragma unroll
        for (int r = 0; r < 4; r++) acc[nt][r] = 0.0f;

    const uint32_t aAddr = (uint32_t)(((g >> 1) * 8 + rr) * 144 + (d0 + (g & 1) * 8) * 2);
    const uint32_t bAddr = (uint32_t)(((g & 1) * 8 + rr) * 144 + (m0 + (g >> 1) * 8) * 2);

#pragma unroll
    for (int ks = 0; ks < 8; ks++) {
        uint32_t a0, a1, a2, a3;
        LDMATRIX_X4_TRANS(a0, a1, a2, a3, kbase + aAddr + (uint32_t)(ks * 16 * 144));
#pragma unroll
        for (int p = 0; p < 2; p++) {
            uint32_t b0, b1, b2, b3;
            LDMATRIX_X4_TRANS(b0, b1, b2, b3,
                              vbase + bAddr + (uint32_t)(ks * 16 * 144) + (uint32_t)(p * 32));
            MMA_F16(acc[p * 2],     a0, a1, a2, a3, b0, b1);
            MMA_F16(acc[p * 2 + 1], a0, a1, a2, a3, b2, b3);
        }
    }

    size_t obase = ((size_t)bh * NCHUNK + c) * (DH * DH);
    int row_lo = d0 + gid, row_hi = row_lo + 8;
#pragma unroll
    for (int nt = 0; nt < 4; nt++) {
        int col = m0 + nt * 8 + tig * 2;
        *(float2*)&kvch[obase + (size_t)row_lo * 64 + col] = make_float2(acc[nt][0], acc[nt][1]);
        *(float2*)&kvch[obase + (size_t)row_hi * 64 + col] = make_float2(acc[nt][2], acc[nt][3]);
    }

    // parallel ksum: 256 threads = 4 row-groups x 64 d
    {
        int d = tid & 63, part = tid >> 6;
        float ssum = 0.0f;
        int rbeg = part * 32;
#pragma unroll 8
        for (int r = rbeg; r < rbeg + 32; r++)
            ssum += __half2float(Kh[r * 72 + d]);
        red[part * 64 + d] = ssum;
    }
    __syncthreads();
    if (tid < 64) {
        float t = red[tid] + red[64 + tid] + red[128 + tid] + red[192 + tid];
        ksch[((size_t)bh * NCHUNK + c) * DH + tid] = t;
    }
}

// ---------------- pass B: exclusive prefix over chunks (batched loads) ----------------
__global__ void prefix_kernel(float* __restrict__ kvch, float* __restrict__ ksch) {
    int bh = blockIdx.x;
    for (int e = threadIdx.x; e < DH * DH; e += blockDim.x) {
        float* p = &kvch[(size_t)bh * NCHUNK * (DH * DH) + e];
        float r[NCHUNK];
#pragma unroll
        for (int c = 0; c < NCHUNK; c++) r[c] = p[(size_t)c * (DH * DH)];
        float acc = 0.0f;
#pragma unroll
        for (int c = 0; c < NCHUNK; c++) {
            float t = r[c];
            p[(size_t)c * (DH * DH)] = acc;
            acc += t;
        }
    }
    if (threadIdx.x < DH) {
        float* p = &ksch[(size_t)bh * NCHUNK * DH + threadIdx.x];
        float r[NCHUNK];
#pragma unroll
        for (int c = 0; c < NCHUNK; c++) r[c] = p[(size_t)c * DH];
        float acc = 0.0f;
#pragma unroll
        for (int c = 0; c < NCHUNK; c++) {
            float t = r[c];
            p[(size_t)c * DH] = acc;
            acc += t;
        }
    }
}

// ---------------- pass C: tensor-core per-chunk output ----------------
#define PQU 36
#define PSU 68
__global__ __launch_bounds__(256) void chunk_out_tc(
        const __half* __restrict__ qh, const __half* __restrict__ kh,
        const __half* __restrict__ vh, const float* __restrict__ kvch,
        const float* __restrict__ ksch, __half* __restrict__ attn) {
    extern __shared__ char smem[];
    __half* Qh   = (__half*)smem;
    __half* Kh   = (__half*)(smem + 18432);
    __half* Vh   = (__half*)(smem + 36864);
    __half* KVph = (__half*)(smem + 55296);
    __half* Sh   = (__half*)(smem + 64512);
    float* rowsum = (float*)(smem + 99328);
    float* den    = (float*)(smem + 99840);
    float* KSp    = (float*)(smem + 100352);

    const int blk = blockIdx.x;
    const int c  = blk % NCHUNK;
    const int bh = blk / NCHUNK;
    const int b  = bh / HEADS;
    const int h  = bh % HEADS;
    const int tid = threadIdx.x;
    const int warp = tid >> 5, lane = tid & 31;
    const int gid = lane >> 2, tig = lane & 3;
    const int g = lane >> 3, rr = lane & 7;

    size_t gbase = (((size_t)bh) * SEQ + (size_t)c * CHUNK) * DH;
    for (int i = tid; i < 1024; i += 256) {
        int row = i >> 3, c16 = (i & 7) * 16;
        *(float4*)((char*)Qh + row * 144 + c16) = ((const float4*)(qh + gbase))[i];
        *(float4*)((char*)Kh + row * 144 + c16) = ((const float4*)(kh + gbase))[i];
        *(float4*)((char*)Vh + row * 144 + c16) = ((const float4*)(vh + gbase))[i];
    }
    {
        size_t kvbase = ((size_t)bh * NCHUNK + c) * (DH * DH);
        for (int i = tid; i < 2048; i += 256) {
            int d = i >> 5, m2 = i & 31;
            float2 f = ((const float2*)(kvch + kvbase))[i];
            *(uint32_t*)((char*)KVph + d * 144 + m2 * 4) =
                h2_to_u32(__floats2half2_rn(f.x, f.y));
        }
        if (tid < 64)
            KSp[tid] = ksch[((size_t)bh * NCHUNK + c) * DH + tid];
    }
    __syncthreads();

    const uint32_t* Qu = (const uint32_t*)Qh;
    uint32_t* Su = (uint32_t*)Sh;
    const uint32_t qbase = smem_u32p(Qh);
    const uint32_t kbase = smem_u32p(Kh);
    const uint32_t sbase = smem_u32p(Sh);
    const int r0 = warp * 16;

    const uint32_t aRowQ = (uint32_t)((r0 + (g & 1) * 8 + rr) * 144 + (g >> 1) * 16);
    const uint32_t aRowS = (uint32_t)((r0 + (g & 1) * 8 + rr) * 272 + (g >> 1) * 16);
    const uint32_t bRowK = (uint32_t)(((g >> 1) * 8 + rr) * 144 + (g & 1) * 16);

    {
        float acc1[16][4];
#pragma unroll
        for (int nt = 0; nt < 16; nt++)
#pragma unroll
            for (int r = 0; r < 4; r++) acc1[nt][r] = 0.0f;

#pragma unroll
        for (int ks = 0; ks < 4; ks++) {
            uint32_t aq[4];
            LDMATRIX_X4(aq[0], aq[1], aq[2], aq[3], qbase + aRowQ + ks * 32);
#pragma unroll
            for (int p = 0; p < 8; p++) {
                uint32_t bk[4];
                LDMATRIX_X4(bk[0], bk[1], bk[2], bk[3],
                            kbase + bRowK + (uint32_t)(p * 16 * 144) + ks * 32);
                MMA_F16(acc1[2 * p],     aq[0], aq[1], aq[2], aq[3], bk[0], bk[1]);
                MMA_F16(acc1[2 * p + 1], aq[0], aq[1], aq[2], aq[3], bk[2], bk[3]);
            }
        }

        int row_lo = r0 + gid, row_hi = row_lo + 8;
        float sum_lo = 0.0f, sum_hi = 0.0f;
#pragma unroll
        for (int nt = 0; nt < 16; nt++) {
            int c0 = nt * 8 + tig * 2, c1 = c0 + 1;
            float v0 = (c0 <= row_lo) ? acc1[nt][0] : 0.0f;
            float v1 = (c1 <= row_lo) ? acc1[nt][1] : 0.0f;
            float v2 = (c0 <= row_hi) ? acc1[nt][2] : 0.0f;
            float v3 = (c1 <= row_hi) ? acc1[nt][3] : 0.0f;
            sum_lo += v0 + v1;
            sum_hi += v2 + v3;
            Su[row_lo * PSU + nt * 4 + tig] = h2_to_u32(__floats2half2_rn(v0, v1));
            Su[row_hi * PSU + nt * 4 + tig] = h2_to_u32(__floats2half2_rn(v2, v3));
        }
        sum_lo += __shfl_xor_sync(0xffffffff, sum_lo, 1);
        sum_lo += __shfl_xor_sync(0xffffffff, sum_lo, 2);
        sum_hi += __shfl_xor_sync(0xffffffff, sum_hi, 1);
        sum_hi += __shfl_xor_sync(0xffffffff, sum_hi, 2);
        if (tig == 0) { rowsum[row_lo] = sum_lo; rowsum[row_hi] = sum_hi; }
    }
    __syncthreads();

    if (tid < 128) {
        float dsum = rowsum[tid];
        const uint32_t* Qr = Qu + tid * PQU;
#pragma unroll
        for (int dd = 0; dd < 32; dd++) {
            float2 qv = __half22float2(u32_to_h2(Qr[dd]));
            dsum += qv.x * KSp[dd * 2] + qv.y * KSp[dd * 2 + 1];
        }
        den[tid] = 1.0f / fmaxf(dsum, 1e-6f);
    }
    __syncthreads();

    {
        float acc2[8][4];
#pragma unroll
        for (int nt = 0; nt < 8; nt++)
#pragma unroll
            for (int r = 0; r < 4; r++) acc2[nt][r] = 0.0f;

        const uint32_t vbase = smem_u32p(Vh);
        const uint32_t kvbase = smem_u32p(KVph);
        const int sel = lane >> 3;
        const int srow_in = ((sel & 1) << 3) + (lane & 7);
        const int ncol_in = (sel >> 1) << 3;

#pragma unroll
        for (int ks = 0; ks < 8; ks++) {
            uint32_t as[4];
            LDMATRIX_X4(as[0], as[1], as[2], as[3], sbase + aRowS + ks * 32);
#pragma unroll
            for (int nt2 = 0; nt2 < 4; nt2++) {
                uint32_t addr = vbase + (uint32_t)((ks * 16 + srow_in) * 144 + (nt2 * 16 + ncol_in) * 2);
                uint32_t b0, b1, b2, b3;
                LDMATRIX_X4_TRANS(b0, b1, b2, b3, addr);
                MMA_F16(acc2[nt2 * 2],     as[0], as[1], as[2], as[3], b0, b1);
                MMA_F16(acc2[nt2 * 2 + 1], as[0], as[1], as[2], as[3], b2, b3);
            }
        }
#pragma unroll
        for (int ks = 0; ks < 4; ks++) {
            uint32_t aq[4];
            LDMATRIX_X4(aq[0], aq[1], aq[2], aq[3], qbase + aRowQ + ks * 32);
#pragma unroll
            for (int nt2 = 0; nt2 < 4; nt2++) {
                uint32_t addr = kvbase + (uint32_t)((ks * 16 + srow_in) * 144 + (nt2 * 16 + ncol_in) * 2);
                uint32_t b0, b1, b2, b3;
                LDMATRIX_X4_TRANS(b0, b1, b2, b3, addr);
                MMA_F16(acc2[nt2 * 2],     aq[0], aq[1], aq[2], aq[3], b0, b1);
                MMA_F16(acc2[nt2 * 2 + 1], aq[0], aq[1], aq[2], aq[3], b2, b3);
            }
        }

        int row_lo = r0 + gid, row_hi = row_lo + 8;
        float inv_lo = den[row_lo], inv_hi = den[row_hi];
        size_t obL = ((size_t)b * SEQ + (size_t)c * CHUNK + row_lo) * DIM + h * 64;
        size_t obH = obL + (size_t)8 * DIM;
#pragma unroll
        for (int nt = 0; nt < 8; nt++) {
            int c0 = nt * 8 + tig * 2;
            *(__half2*)(attn + obL + c0) = __floats2half2_rn(acc2[nt][0] * inv_lo, acc2[nt][1] * inv_lo);
            *(__half2*)(attn + obH + c0) = __floats2half2_rn(acc2[nt][2] * inv_hi, acc2[nt][3] * inv_hi);
        }
    }
}

// ---------------- host launch ----------------
extern "C" void kernel_launch(void* const* d_in, const int* in_sizes, int n_in,
                              void* d_out, int out_size) {
    const float* x    = (const float*)d_in[0];
    const float* wqkv = (const float*)d_in[1];
    const float* wout = (const float*)d_in[2];
    float* out = (float*)d_out;

    float *kvch, *ksch;
    float2* rope;
    __half *xh, *wqkvT, *woutT, *qh, *kh, *vh, *attnh;
    cudaGetSymbolAddress((void**)&xh,    g_xh);
    cudaGetSymbolAddress((void**)&wqkvT, g_wqkvT);
    cudaGetSymbolAddress((void**)&woutT, g_woutT);
    cudaGetSymbolAddress((void**)&qh,    g_qh);
    cudaGetSymbolAddress((void**)&kh,    g_kh);
    cudaGetSymbolAddress((void**)&vh,    g_vh);
    cudaGetSymbolAddress((void**)&attnh, g_attnh);
    cudaGetSymbolAddress((void**)&kvch,  g_kvch);
    cudaGetSymbolAddress((void**)&ksch,  g_ksch);
    cudaGetSymbolAddress((void**)&rope,  g_rope);

    const size_t smemG  = 3 * STAGE_B;               // 61440 B
    const size_t smemGQ = 128 * 132 * sizeof(float); // 67584 B (covers pipeline too)
    const size_t smemS  = 2 * 18432 + 1024;          // +red buffer
    const size_t smemC  = 100608;
    cudaFuncSetAttribute(gemm_f16,      cudaFuncAttributeMaxDynamicSharedMemorySize, (int)smemG);
    cudaFuncSetAttribute(gemm_qkv,      cudaFuncAttributeMaxDynamicSharedMemorySize, (int)smemGQ);
    cudaFuncSetAttribute(chunk_sums_tc, cudaFuncAttributeMaxDynamicSharedMemorySize, (int)smemS);
    cudaFuncSetAttribute(chunk_out_tc,  cudaFuncAttributeMaxDynamicSharedMemorySize, (int)smemC);

    // 0) prep (x->fp16 + rope table in one launch) + weight transposes
    {
        int nblk = (N2X + SEQ * 32) / 256;
        prep_kernel<<<nblk, 256>>>((const float2*)x, (__half2*)xh, rope);
        transpose_f16<<<dim3(3 * DIM / 32, DIM / 32), dim3(32, 8)>>>(wqkv, wqkvT, DIM, 3 * DIM);
        transpose_f16<<<dim3(DIM / 32, DIM / 32), dim3(32, 8)>>>(wout, woutT, DIM, DIM);
    }

    // 1) fused qkv GEMM + RoPE(table) + ELU -> fp16 q/k/v in [bh][n][64]
    gemm_qkv<<<dim3(3072 / 128, 16384 / 128), 256, smemGQ>>>(xh, wqkvT, rope, qh, kh, vh);
    // 2) per-chunk K^T V sums (tensor cores, fp32 out)
    chunk_sums_tc<<<BH * NCHUNK, 256, smemS>>>(kh, vh, kvch, ksch);
    // 3) exclusive prefix across chunks
    prefix_kernel<<<BH, 1024>>>(kvch, ksch);
    // 4) per-chunk outputs via tensor cores
    chunk_out_tc<<<BH * NCHUNK, 256, smemC>>>(qh, kh, vh, kvch, ksch, attnh);
    // 5) final = attnh @ woutT^T
    gemm_f16<<<dim3(1024 / 128, 16384 / 128), 256, smemG>>>(attnh, woutT, out, BATCH * SEQ, DIM, DIM);
}

// round 15
// speedup vs baseline: 1.1440x; 1.0001x over previous
#include <cuda_runtime.h>
#include <cuda_fp16.h>
#include <math.h>
#include <stdint.h>

#define BATCH 4
#define SEQ   4096
#define DIM   1024
#define HEADS 16
#define DH    64
#define CHUNK 128
#define NCHUNK 32
#define BH    (BATCH*HEADS)
#define FEAT_SCALE 0.35355339059327373f  // 64^-0.25

// ---------------- scratch (device globals; no allocation allowed) ----------------
__device__ __half g_xh   [BATCH*SEQ*DIM];     // fp16 x
__device__ __half g_wqkvT[3*DIM*DIM];         // K-major fp16
__device__ __half g_woutT[DIM*DIM];           // K-major fp16
__device__ __half g_qh  [BH*SEQ*DH];          // featurized q (fp16)
__device__ __half g_kh  [BH*SEQ*DH];          // featurized k (fp16)
__device__ __half g_vh  [BH*SEQ*DH];          // v (fp16)
__device__ __half g_attnh[BATCH*SEQ*DIM];     // attention out, fp16
__device__ float  g_kvch[BH*NCHUNK*DH*DH];
__device__ float  g_ksch[BH*NCHUNK*DH];
__device__ float2 g_rope[SEQ*32];             // (cos*SCALE, sin*SCALE) per (n, d)

// ---------------- helpers ----------------
__device__ __forceinline__ uint32_t h2_to_u32(__half2 h) {
    __half2_raw r = *(__half2_raw*)&h;
    return (uint32_t)r.x | ((uint32_t)r.y << 16);
}
__device__ __forceinline__ __half2 u32_to_h2(uint32_t u) {
    __half2_raw r;
    r.x = (unsigned short)(u & 0xFFFF);
    r.y = (unsigned short)(u >> 16);
    return *(__half2*)&r;
}
__device__ __forceinline__ void cpasync16(void* dst, const void* src) {
    unsigned d = (unsigned)__cvta_generic_to_shared(dst);
    asm volatile("cp.async.ca.shared.global [%0], [%1], 16;" :: "r"(d), "l"(src));
}
#define CP_COMMIT()  asm volatile("cp.async.commit_group;")
#define CP_WAIT1()   asm volatile("cp.async.wait_group 1;")

#define MMA_F16(acc, a0, a1, a2, a3, b0, b1) \
    asm volatile("mma.sync.aligned.m16n8k16.row.col.f32.f16.f16.f32 " \
        "{%0,%1,%2,%3}, {%4,%5,%6,%7}, {%8,%9}, {%0,%1,%2,%3};" \
        : "+f"((acc)[0]), "+f"((acc)[1]), "+f"((acc)[2]), "+f"((acc)[3]) \
        : "r"(a0), "r"(a1), "r"(a2), "r"(a3), "r"(b0), "r"(b1))

#define LDMATRIX_X4(r0, r1, r2, r3, addr) \
    asm volatile("ldmatrix.sync.aligned.m8n8.x4.shared.b16 {%0,%1,%2,%3}, [%4];" \
        : "=r"(r0), "=r"(r1), "=r"(r2), "=r"(r3) : "r"(addr))

#define LDMATRIX_X4_TRANS(r0, r1, r2, r3, addr) \
    asm volatile("ldmatrix.sync.aligned.m8n8.x4.trans.shared.b16 {%0,%1,%2,%3}, [%4];" \
        : "=r"(r0), "=r"(r1), "=r"(r2), "=r"(r3) : "r"(addr))

__device__ __forceinline__ uint32_t smem_u32p(const void* p) {
    return (uint32_t)__cvta_generic_to_shared(p);
}
__device__ __forceinline__ float exp_fast(float y) {   // exp(y), |err| ~2ulp
    float r;
    asm("ex2.approx.f32 %0, %1;" : "=f"(r) : "f"(y * 1.4426950408889634f));
    return r;
}

// fp32 sincos, FMA Cody-Waite range reduction (accurate ~1e-7 for ang < 5000)
__device__ __forceinline__ void rope_sincos_f(float ang, float& s, float& c) {
    float qf = rintf(ang * 0.63661977f);
    float r = fmaf(-qf, 1.57079637e+0f, ang);
    r = fmaf(qf, 4.37113900e-8f, r);
    int qi = (int)qf & 3;
    float r2 = r * r;
    float sp = r * (1.0f + r2 * (-1.6666667e-1f + r2 * (8.3333337e-3f
              + r2 * (-1.9841270e-4f + r2 * 2.7557319e-6f))));
    float cp = 1.0f + r2 * (-0.5f + r2 * (4.1666668e-2f
              + r2 * (-1.3888889e-3f + r2 * 2.4801587e-5f)));
    switch (qi) {
        case 0:  s =  sp; c =  cp; break;
        case 1:  s =  cp; c = -sp; break;
        case 2:  s = -sp; c = -cp; break;
        default: s = -cp; c =  sp; break;
    }
}

// ---------------- prep: x->fp16 conversion + rope table (one launch) ----------------
#define N2X ((BATCH*SEQ*DIM)/2)
__global__ void prep_kernel(const float2* __restrict__ in, __half2* __restrict__ out,
                            float2* __restrict__ tbl) {
    int i = blockIdx.x * blockDim.x + threadIdx.x;
    if (i < N2X) {
        out[i] = __float22half2_rn(in[i]);
    } else {
        int idx = i - N2X;                     // SEQ*32 entries
        int d = idx & 31;
        int n = idx >> 5;
        float inv_f = (float)exp(-(double)d * (9.210340371976184 / 32.0));
        float ang = (float)n * inv_f;
        float s, c;
        rope_sincos_f(ang, s, c);
        tbl[idx] = make_float2(c * FEAT_SCALE, s * FEAT_SCALE);
    }
}

__global__ void transpose_f16(const float* __restrict__ W, __half* __restrict__ WT,
                              int K, int Nn) {
    __shared__ float t[32][33];
    int n0 = blockIdx.x * 32, k0 = blockIdx.y * 32;
    int tx = threadIdx.x, ty = threadIdx.y;
#pragma unroll
    for (int i = 0; i < 32; i += 8)
        t[ty + i][tx] = W[(size_t)(k0 + ty + i) * Nn + n0 + tx];
    __syncthreads();
#pragma unroll
    for (int i = 0; i < 32; i += 8)
        WT[(size_t)(n0 + ty + i) * K + k0 + tx] = __float2half(t[tx][ty + i]);
}

// ---------------- generic fp16 GEMM (128x128, single sync/iter) ----------------
#define STAGE_B 20480      // bytes per stage: A 10240 + B 10240 (pitch 80 B)
__global__ __launch_bounds__(256) void gemm_f16(
        const __half* __restrict__ A, const __half* __restrict__ BT,
        float* __restrict__ C, int M, int Nn, int K) {
    extern __shared__ char smc[];
    const int tid = threadIdx.x;
    const int bx = blockIdx.x, by = blockIdx.y;
    const int warp = tid >> 5, lane = tid & 31;
    const int gid = lane >> 2, tig = lane & 3;
    const int g = lane >> 3, rr = lane & 7;
    const int warpM = warp & 1, warpN = warp >> 1;
    const int mBase = warpM * 64;
    const int nBase = warpN * 32;

    const __half* Ab = A  + (size_t)(by * 128) * K;
    const __half* Bb = BT + (size_t)(bx * 128) * K;
    const uint32_t smbase = smem_u32p(smc);

    float acc[4][4][4];
#pragma unroll
    for (int mi = 0; mi < 4; mi++)
#pragma unroll
        for (int nj = 0; nj < 4; nj++)
#pragma unroll
            for (int r = 0; r < 4; r++) acc[mi][nj][r] = 0.0f;

    const int KT = K >> 5;

    auto load_tile = [&](int kt, char* buf) {
        char* As = buf;
        char* Bs = buf + 10240;
        int k0 = kt * 32;
#pragma unroll
        for (int i = 0; i < 2; i++) {
            int c = i * 256 + tid;
            int m = c >> 2, k8 = (c & 3) * 8;
            cpasync16(As + m * 80 + k8 * 2, Ab + (size_t)m * K + k0 + k8);
        }
#pragma unroll
        for (int i = 0; i < 2; i++) {
            int c = i * 256 + tid;
            int n = c >> 2, k8 = (c & 3) * 8;
            cpasync16(Bs + n * 80 + k8 * 2, Bb + (size_t)n * K + k0 + k8);
        }
    };

    load_tile(0, smc);
    CP_COMMIT();
    load_tile(1, smc + STAGE_B);
    CP_COMMIT();

    const uint32_t aRow = (uint32_t)((mBase + (g & 1) * 8 + rr) * 80) + (uint32_t)((g >> 1) * 16);
    const uint32_t bRow = (uint32_t)((nBase + (g >> 1) * 8 + rr) * 80) + (uint32_t)((g & 1) * 16);

    for (int kt = 0; kt < KT; kt++) {
        CP_WAIT1();
        __syncthreads();
        if (kt + 2 < KT) load_tile(kt + 2, smc + ((kt + 2) % 3) * STAGE_B);
        CP_COMMIT();

        uint32_t ab = smbase + (uint32_t)((kt % 3) * STAGE_B);
        uint32_t bb = ab + 10240;

#pragma unroll
        for (int s = 0; s < 2; s++) {
            uint32_t af[4][4];
            uint32_t bq[2][4];
            uint32_t aoff = ab + aRow + s * 32;
            uint32_t boff = bb + bRow + s * 32;
#pragma unroll
            for (int mi = 0; mi < 4; mi++)
                LDMATRIX_X4(af[mi][0], af[mi][1], af[mi][2], af[mi][3], aoff + mi * (16 * 80));
#pragma unroll
            for (int p = 0; p < 2; p++)
                LDMATRIX_X4(bq[p][0], bq[p][1], bq[p][2], bq[p][3], boff + p * (16 * 80));
#pragma unroll
            for (int mi = 0; mi < 4; mi++)
#pragma unroll
                for (int nj = 0; nj < 4; nj++)
                    MMA_F16(acc[mi][nj], af[mi][0], af[mi][1], af[mi][2], af[mi][3],
                            bq[nj >> 1][(nj & 1) * 2], bq[nj >> 1][(nj & 1) * 2 + 1]);
        }
    }

#pragma unroll
    for (int mi = 0; mi < 4; mi++) {
        int row = by * 128 + mBase + mi * 16 + gid;
#pragma unroll
        for (int nj = 0; nj < 4; nj++) {
            int col = bx * 128 + nBase + nj * 8 + tig * 2;
            *(float2*)(C + (size_t)row * Nn + col)       = make_float2(acc[mi][nj][0], acc[mi][nj][1]);
            *(float2*)(C + (size_t)(row + 8) * Nn + col) = make_float2(acc[mi][nj][2], acc[mi][nj][3]);
        }
    }
}

// ---------------- fused QKV GEMM + RoPE(table) + ELU featurize ----------------
__global__ __launch_bounds__(256) void gemm_qkv(
        const __half* __restrict__ A, const __half* __restrict__ BT,
        const float2* __restrict__ rope,
        __half* __restrict__ qh, __half* __restrict__ kh, __half* __restrict__ vh) {
    extern __shared__ char smc[];
    const int K = DIM;
    const int tid = threadIdx.x;
    const int bx = blockIdx.x, by = blockIdx.y;
    const int warp = tid >> 5, lane = tid & 31;
    const int gid = lane >> 2, tig = lane & 3;
    const int g = lane >> 3, rr = lane & 7;
    const int warpM = warp & 1, warpN = warp >> 1;
    const int mBase = warpM * 64;
    const int nBase = warpN * 32;

    const __half* Ab = A + (size_t)(by * 128) * K;
    const __half* Bb = BT + (size_t)(bx * 128) * K;
    const uint32_t smbase = smem_u32p(smc);

    float acc[4][4][4];
#pragma unroll
    for (int mi = 0; mi < 4; mi++)
#pragma unroll
        for (int nj = 0; nj < 4; nj++)
#pragma unroll
            for (int r = 0; r < 4; r++) acc[mi][nj][r] = 0.0f;

    const int KT = K >> 5;

    auto load_tile = [&](int kt, char* buf) {
        char* As = buf;
        char* Bs = buf + 10240;
        int k0 = kt * 32;
#pragma unroll
        for (int i = 0; i < 2; i++) {
            int c = i * 256 + tid;
            int m = c >> 2, k8 = (c & 3) * 8;
            cpasync16(As + m * 80 + k8 * 2, Ab + (size_t)m * K + k0 + k8);
        }
#pragma unroll
        for (int i = 0; i < 2; i++) {
            int c = i * 256 + tid;
            int n = c >> 2, k8 = (c & 3) * 8;
            cpasync16(Bs + n * 80 + k8 * 2, Bb + (size_t)n * K + k0 + k8);
        }
    };

    load_tile(0, smc);
    CP_COMMIT();
    load_tile(1, smc + STAGE_B);
    CP_COMMIT();

    const uint32_t aRow = (uint32_t)((mBase + (g & 1) * 8 + rr) * 80) + (uint32_t)((g >> 1) * 16);
    const uint32_t bRow = (uint32_t)((nBase + (g >> 1) * 8 + rr) * 80) + (uint32_t)((g & 1) * 16);

    for (int kt = 0; kt < KT; kt++) {
        CP_WAIT1();
        __syncthreads();
        if (kt + 2 < KT) load_tile(kt + 2, smc + ((kt + 2) % 3) * STAGE_B);
        CP_COMMIT();

        uint32_t ab = smbase + (uint32_t)((kt % 3) * STAGE_B);
        uint32_t bb = ab + 10240;

#pragma unroll
        for (int s = 0; s < 2; s++) {
            uint32_t af[4][4];
            uint32_t bq[2][4];
            uint32_t aoff = ab + aRow + s * 32;
            uint32_t boff = bb + bRow + s * 32;
#pragma unroll
            for (int mi = 0; mi < 4; mi++)
                LDMATRIX_X4(af[mi][0], af[mi][1], af[mi][2], af[mi][3], aoff + mi * (16 * 80));
#pragma unroll
            for (int p = 0; p < 2; p++)
                LDMATRIX_X4(bq[p][0], bq[p][1], bq[p][2], bq[p][3], boff + p * (16 * 80));
#pragma unroll
            for (int mi = 0; mi < 4; mi++)
#pragma unroll
                for (int nj = 0; nj < 4; nj++)
                    MMA_F16(acc[mi][nj], af[mi][0], af[mi][1], af[mi][2], af[mi][3],
                            bq[nj >> 1][(nj & 1) * 2], bq[nj >> 1][(nj & 1) * 2 + 1]);
        }
    }

    // ---- epilogue: stage tile fp32, featurize via table, store fp16 ----
    __syncthreads();
    float* St = (float*)smc;         // 128 x pitch 132 floats
#pragma unroll
    for (int mi = 0; mi < 4; mi++) {
        int r = mBase + mi * 16 + gid;
#pragma unroll
        for (int nj = 0; nj < 4; nj++) {
            int ccol = nBase + nj * 8 + tig * 2;
            *(float2*)&St[r * 132 + ccol]       = make_float2(acc[mi][nj][0], acc[mi][nj][1]);
            *(float2*)&St[(r + 8) * 132 + ccol] = make_float2(acc[mi][nj][2], acc[mi][nj][3]);
        }
    }
    __syncthreads();

    const int sel   = bx >> 3;           // 0=q, 1=k, 2=v
    const int hbase = (bx & 7) * 2;
    const int d     = tid & 31;
    const int hh    = (tid >> 5) & 1;
    const int rbase = tid >> 6;          // 0..3
    const int bb    = by >> 5;           // batch
    const int n0    = (by * 128) & 4095;

    __half* dst = (sel == 0) ? qh : ((sel == 1) ? kh : vh);

#pragma unroll 4
    for (int k = 0; k < 32; k++) {
        int row = rbase + k * 4;
        float x1 = St[row * 132 + hh * 64 + d];
        float x2 = St[row * 132 + hh * 64 + d + 32];
        float f1, f2;
        if (sel == 2) {
            f1 = x1; f2 = x2;
        } else {
            float2 cs = rope[(n0 + row) * 32 + d];     // (c*S, s*S)
            float y1 = x1 * cs.x - x2 * cs.y;
            float y2 = x1 * cs.y + x2 * cs.x;
            f1 = (y1 > 0.0f) ? y1 + 1.0f : exp_fast(y1);
            f2 = (y2 > 0.0f) ? y2 + 1.0f : exp_fast(y2);
        }
        size_t ob = (((size_t)(bb * HEADS + hbase + hh)) * SEQ + (n0 + row)) * DH + d;
        dst[ob]      = __float2half(f1);
        dst[ob + 32] = __float2half(f2);
    }
}

// ---------------- pass A: tensor-core per-chunk K^T V (64x64) and sum(k) ----------------
__global__ __launch_bounds__(256) void chunk_sums_tc(
        const __half* __restrict__ kh, const __half* __restrict__ vh,
        float* __restrict__ kvch, float* __restrict__ ksch) {
    extern __shared__ char smem[];
    __half* Kh = (__half*)smem;              // 128 x 144 B = 18432
    __half* Vh = (__half*)(smem + 18432);    // 18432
    float* red = (float*)(smem + 36864);     // [4][64] = 1024 B

    const int blk = blockIdx.x;
    const int c  = blk % NCHUNK;
    const int bh = blk / NCHUNK;
    const int tid = threadIdx.x;
    const int warp = tid >> 5, lane = tid & 31;
    const int gid = lane >> 2, tig = lane & 3;
    const int g = lane >> 3, rr = lane & 7;

    size_t gbase = (((size_t)bh) * SEQ + (size_t)c * CHUNK) * DH;
    for (int i = tid; i < 1024; i += 256) {
        int row = i >> 3, c16 = (i & 7) * 16;
        *(float4*)((char*)Kh + row * 144 + c16) = ((const float4*)(kh + gbase))[i];
        *(float4*)((char*)Vh + row * 144 + c16) = ((const float4*)(vh + gbase))[i];
    }
    __syncthreads();

    const uint32_t kbase = smem_u32p(Kh);
    const uint32_t vbase = smem_u32p(Vh);
    const int d0 = (warp & 3) * 16;
    const int m0 = (warp >> 2) * 32;

    float acc[4][4];
#pragma unroll
    for (int nt = 0; nt < 4; nt++)
#pragma unroll
        for (int r = 0; r < 4; r++) acc[nt][r] = 0.0f;

    const uint32_t aAddr = (uint32_t)(((g >> 1) * 8 + rr) * 144 + (d0 + (g & 1) * 8) * 2);
    const uint32_t bAddr = (uint32_t)(((g & 1) * 8 + rr) * 144 + (m0 + (g >> 1) * 8) * 2);

#pragma unroll
    for (int ks = 0; ks < 8; ks++) {
        uint32_t a0, a1, a2, a3;
        LDMATRIX_X4_TRANS(a0, a1, a2, a3, kbase + aAddr + (uint32_t)(ks * 16 * 144));
#pragma unroll
        for (int p = 0; p < 2; p++) {
            uint32_t b0, b1, b2, b3;
            LDMATRIX_X4_TRANS(b0, b1, b2, b3,
                              vbase + bAddr + (uint32_t)(ks * 16 * 144) + (uint32_t)(p * 32));
            MMA_F16(acc[p * 2],     a0, a1, a2, a3, b0, b1);
            MMA_F16(acc[p * 2 + 1], a0, a1, a2, a3, b2, b3);
        }
    }

    size_t obase = ((size_t)bh * NCHUNK + c) * (DH * DH);
    int row_lo = d0 + gid, row_hi = row_lo + 8;
#pragma unroll
    for (int nt = 0; nt < 4; nt++) {
        int col = m0 + nt * 8 + tig * 2;
        *(float2*)&kvch[obase + (size_t)row_lo * 64 + col] = make_float2(acc[nt][0], acc[nt][1]);
        *(float2*)&kvch[obase + (size_t)row_hi * 64 + col] = make_float2(acc[nt][2], acc[nt][3]);
    }

    // parallel ksum: 256 threads = 4 row-groups x 64 d
    {
        int d = tid & 63, part = tid >> 6;
        float ssum = 0.0f;
        int rbeg = part * 32;
#pragma unroll 8
        for (int r = rbeg; r < rbeg + 32; r++)
            ssum += __half2float(Kh[r * 72 + d]);
        red[part * 64 + d] = ssum;
    }
    __syncthreads();
    if (tid < 64) {
        float t = red[tid] + red[64 + tid] + red[128 + tid] + red[192 + tid];
        ksch[((size_t)bh * NCHUNK + c) * DH + tid] = t;
    }
}

// ---------------- pass B: exclusive prefix over chunks (batched loads) ----------------
__global__ void prefix_kernel(float* __restrict__ kvch, float* __restrict__ ksch) {
    int bh = blockIdx.x;
    for (int e = threadIdx.x; e < DH * DH; e += blockDim.x) {
        float* p = &kvch[(size_t)bh * NCHUNK * (DH * DH) + e];
        float r[NCHUNK];
#pragma unroll
        for (int c = 0; c < NCHUNK; c++) r[c] = p[(size_t)c * (DH * DH)];
        float acc = 0.0f;
#pragma unroll
        for (int c = 0; c < NCHUNK; c++) {
            float t = r[c];
            p[(size_t)c * (DH * DH)] = acc;
            acc += t;
        }
    }
    if (threadIdx.x < DH) {
        float* p = &ksch[(size_t)bh * NCHUNK * DH + threadIdx.x];
        float r[NCHUNK];
#pragma unroll
        for (int c = 0; c < NCHUNK; c++) r[c] = p[(size_t)c * DH];
        float acc = 0.0f;
#pragma unroll
        for (int c = 0; c < NCHUNK; c++) {
            float t = r[c];
            p[(size_t)c * DH] = acc;
            acc += t;
        }
    }
}

// ---------------- pass C: tensor-core per-chunk output ----------------
#define PQU 36
#define PSU 68
__global__ __launch_bounds__(256) void chunk_out_tc(
        const __half* __restrict__ qh, const __half* __restrict__ kh,
        const __half* __restrict__ vh, const float* __restrict__ kvch,
        const float* __restrict__ ksch, __half* __restrict__ attn) {
    extern __shared__ char smem[];
    __half* Qh   = (__half*)smem;
    __half* Kh   = (__half*)(smem + 18432);
    __half* Vh   = (__half*)(smem + 36864);
    __half* KVph = (__half*)(smem + 55296);
    __half* Sh   = (__half*)(smem + 64512);
    float* rowsum = (float*)(smem + 99328);
    float* den    = (float*)(smem + 99840);
    float* KSp    = (float*)(smem + 100352);

    const int blk = blockIdx.x;
    const int c  = blk % NCHUNK;
    const int bh = blk / NCHUNK;
    const int b  = bh / HEADS;
    const int h  = bh % HEADS;
    const int tid = threadIdx.x;
    const int warp = tid >> 5, lane = tid & 31;
    const int gid = lane >> 2, tig = lane & 3;
    const int g = lane >> 3, rr = lane & 7;

    size_t gbase = (((size_t)bh) * SEQ + (size_t)c * CHUNK) * DH;
    for (int i = tid; i < 1024; i += 256) {
        int row = i >> 3, c16 = (i & 7) * 16;
        *(float4*)((char*)Qh + row * 144 + c16) = ((const float4*)(qh + gbase))[i];
        *(float4*)((char*)Kh + row * 144 + c16) = ((const float4*)(kh + gbase))[i];
        *(float4*)((char*)Vh + row * 144 + c16) = ((const float4*)(vh + gbase))[i];
    }
    {
        size_t kvbase = ((size_t)bh * NCHUNK + c) * (DH * DH);
        for (int i = tid; i < 2048; i += 256) {
            int d = i >> 5, m2 = i & 31;
            float2 f = ((const float2*)(kvch + kvbase))[i];
            *(uint32_t*)((char*)KVph + d * 144 + m2 * 4) =
                h2_to_u32(__floats2half2_rn(f.x, f.y));
        }
        if (tid < 64)
            KSp[tid] = ksch[((size_t)bh * NCHUNK + c) * DH + tid];
    }
    __syncthreads();

    const uint32_t* Qu = (const uint32_t*)Qh;
    uint32_t* Su = (uint32_t*)Sh;
    const uint32_t qbase = smem_u32p(Qh);
    const uint32_t kbase = smem_u32p(Kh);
    const uint32_t sbase = smem_u32p(Sh);
    const int r0 = warp * 16;

    const uint32_t aRowQ = (uint32_t)((r0 + (g & 1) * 8 + rr) * 144 + (g >> 1) * 16);
    const uint32_t aRowS = (uint32_t)((r0 + (g & 1) * 8 + rr) * 272 + (g >> 1) * 16);
    const uint32_t bRowK = (uint32_t)(((g >> 1) * 8 + rr) * 144 + (g & 1) * 16);

    {
        float acc1[16][4];
#pragma unroll
        for (int nt = 0; nt < 16; nt++)
#pragma unroll
            for (int r = 0; r < 4; r++) acc1[nt][r] = 0.0f;

#pragma unroll
        for (int ks = 0; ks < 4; ks++) {
            uint32_t aq[4];
            LDMATRIX_X4(aq[0], aq[1], aq[2], aq[3], qbase + aRowQ + ks * 32);
#pragma unroll
            for (int p = 0; p < 8; p++) {
                uint32_t bk[4];
                LDMATRIX_X4(bk[0], bk[1], bk[2], bk[3],
                            kbase + bRowK + (uint32_t)(p * 16 * 144) + ks * 32);
                MMA_F16(acc1[2 * p],     aq[0], aq[1], aq[2], aq[3], bk[0], bk[1]);
                MMA_F16(acc1[2 * p + 1], aq[0], aq[1], aq[2], aq[3], bk[2], bk[3]);
            }
        }

        int row_lo = r0 + gid, row_hi = row_lo + 8;
        float sum_lo = 0.0f, sum_hi = 0.0f;
#pragma unroll
        for (int nt = 0; nt < 16; nt++) {
            int c0 = nt * 8 + tig * 2, c1 = c0 + 1;
            float v0 = (c0 <= row_lo) ? acc1[nt][0] : 0.0f;
            float v1 = (c1 <= row_lo) ? acc1[nt][1] : 0.0f;
            float v2 = (c0 <= row_hi) ? acc1[nt][2] : 0.0f;
            float v3 = (c1 <= row_hi) ? acc1[nt][3] : 0.0f;
            sum_lo += v0 + v1;
            sum_hi += v2 + v3;
            Su[row_lo * PSU + nt * 4 + tig] = h2_to_u32(__floats2half2_rn(v0, v1));
            Su[row_hi * PSU + nt * 4 + tig] = h2_to_u32(__floats2half2_rn(v2, v3));
        }
        sum_lo += __shfl_xor_sync(0xffffffff, sum_lo, 1);
        sum_lo += __shfl_xor_sync(0xffffffff, sum_lo, 2);
        sum_hi += __shfl_xor_sync(0xffffffff, sum_hi, 1);
        sum_hi += __shfl_xor_sync(0xffffffff, sum_hi, 2);
        if (tig == 0) { rowsum[row_lo] = sum_lo; rowsum[row_hi] = sum_hi; }
    }
    __syncthreads();

    if (tid < 128) {
        float dsum = rowsum[tid];
        const uint32_t* Qr = Qu + tid * PQU;
#pragma unroll
        for (int dd = 0; dd < 32; dd++) {
            float2 qv = __half22float2(u32_to_h2(Qr[dd]));
            dsum += qv.x * KSp[dd * 2] + qv.y * KSp[dd * 2 + 1];
        }
        den[tid] = 1.0f / fmaxf(dsum, 1e-6f);
    }
    __syncthreads();

    {
        float acc2[8][4];
#pragma unroll
        for (int nt = 0; nt < 8; nt++)
#pragma unroll
            for (int r = 0; r < 4; r++) acc2[nt][r] = 0.0f;

        const uint32_t vbase = smem_u32p(Vh);
        const uint32_t kvbase = smem_u32p(KVph);
        const int sel = lane >> 3;
        const int srow_in = ((sel & 1) << 3) + (lane & 7);
        const int ncol_in = (sel >> 1) << 3;

#pragma unroll
        for (int ks = 0; ks < 8; ks++) {
            uint32_t as[4];
            LDMATRIX_X4(as[0], as[1], as[2], as[3], sbase + aRowS + ks * 32);
#pragma unroll
            for (int nt2 = 0; nt2 < 4; nt2++) {
                uint32_t addr = vbase + (uint32_t)((ks * 16 + srow_in) * 144 + (nt2 * 16 + ncol_in) * 2);
                uint32_t b0, b1, b2, b3;
                LDMATRIX_X4_TRANS(b0, b1, b2, b3, addr);
                MMA_F16(acc2[nt2 * 2],     as[0], as[1], as[2], as[3], b0, b1);
                MMA_F16(acc2[nt2 * 2 + 1], as[0], as[1], as[2], as[3], b2, b3);
            }
        }
#pragma unroll
        for (int ks = 0; ks < 4; ks++) {
            uint32_t aq[4];
            LDMATRIX_X4(aq[0], aq[1], aq[2], aq[3], qbase + aRowQ + ks * 32);
#pragma unroll
            for (int nt2 = 0; nt2 < 4; nt2++) {
                uint32_t addr = kvbase + (uint32_t)((ks * 16 + srow_in) * 144 + (nt2 * 16 + ncol_in) * 2);
                uint32_t b0, b1, b2, b3;
                LDMATRIX_X4_TRANS(b0, b1, b2, b3, addr);
                MMA_F16(acc2[nt2 * 2],     aq[0], aq[1], aq[2], aq[3], b0, b1);
                MMA_F16(acc2[nt2 * 2 + 1], aq[0], aq[1], aq[2], aq[3], b2, b3);
            }
        }

        int row_lo = r0 + gid, row_hi = row_lo + 8;
        float inv_lo = den[row_lo], inv_hi = den[row_hi];
        size_t obL = ((size_t)b * SEQ + (size_t)c * CHUNK + row_lo) * DIM + h * 64;
        size_t obH = obL + (size_t)8 * DIM;
#pragma unroll
        for (int nt = 0; nt < 8; nt++) {
            int c0 = nt * 8 + tig * 2;
            *(__half2*)(attn + obL + c0) = __floats2half2_rn(acc2[nt][0] * inv_lo, acc2[nt][1] * inv_lo);
            *(__half2*)(attn + obH + c0) = __floats2half2_rn(acc2[nt][2] * inv_hi, acc2[nt][3] * inv_hi);
        }
    }
}

// ---------------- host launch ----------------
extern "C" void kernel_launch(void* const* d_in, const int* in_sizes, int n_in,
                              void* d_out, int out_size) {
    const float* x    = (const float*)d_in[0];
    const float* wqkv = (const float*)d_in[1];
    const float* wout = (const float*)d_in[2];
    float* out = (float*)d_out;

    float *kvch, *ksch;
    float2* rope;
    __half *xh, *wqkvT, *woutT, *qh, *kh, *vh, *attnh;
    cudaGetSymbolAddress((void**)&xh,    g_xh);
    cudaGetSymbolAddress((void**)&wqkvT, g_wqkvT);
    cudaGetSymbolAddress((void**)&woutT, g_woutT);
    cudaGetSymbolAddress((void**)&qh,    g_qh);
    cudaGetSymbolAddress((void**)&kh,    g_kh);
    cudaGetSymbolAddress((void**)&vh,    g_vh);
    cudaGetSymbolAddress((void**)&attnh, g_attnh);
    cudaGetSymbolAddress((void**)&kvch,  g_kvch);
    cudaGetSymbolAddress((void**)&ksch,  g_ksch);
    cudaGetSymbolAddress((void**)&rope,  g_rope);

    const size_t smemG  = 3 * STAGE_B;               // 61440 B
    const size_t smemGQ = 128 * 132 * sizeof(float); // 67584 B (covers pipeline too)
    const size_t smemS  = 2 * 18432 + 1024;          // +red buffer
    const size_t smemC  = 100608;
    cudaFuncSetAttribute(gemm_f16,      cudaFuncAttributeMaxDynamicSharedMemorySize, (int)smemG);
    cudaFuncSetAttribute(gemm_qkv,      cudaFuncAttributeMaxDynamicSharedMemorySize, (int)smemGQ);
    cudaFuncSetAttribute(chunk_sums_tc, cudaFuncAttributeMaxDynamicSharedMemorySize, (int)smemS);
    cudaFuncSetAttribute(chunk_out_tc,  cudaFuncAttributeMaxDynamicSharedMemorySize, (int)smemC);

    // 0) prep (x->fp16 + rope table in one launch) + weight transposes
    {
        int nblk = (N2X + SEQ * 32) / 256;
        prep_kernel<<<nblk, 256>>>((const float2*)x, (__half2*)xh, rope);
        transpose_f16<<<dim3(3 * DIM / 32, DIM / 32), dim3(32, 8)>>>(wqkv, wqkvT, DIM, 3 * DIM);
        transpose_f16<<<dim3(DIM / 32, DIM / 32), dim3(32, 8)>>>(wout, woutT, DIM, DIM);
    }

    // 1) fused qkv GEMM + RoPE(table) + ELU -> fp16 q/k/v in [bh][n][64]
    gemm_qkv<<<dim3(3072 / 128, 16384 / 128), 256, smemGQ>>>(xh, wqkvT, rope, qh, kh, vh);
    // 2) per-chunk K^T V sums (tensor cores, fp32 out)
    chunk_sums_tc<<<BH * NCHUNK, 256, smemS>>>(kh, vh, kvch, ksch);
    // 3) exclusive prefix across chunks
    prefix_kernel<<<BH, 1024>>>(kvch, ksch);
    // 4) per-chunk outputs via tensor cores
    chunk_out_tc<<<BH * NCHUNK, 256, smemC>>>(qh, kh, vh, kvch, ksch, attnh);
    // 5) final = attnh @ woutT^T
    gemm_f16<<<dim3(1024 / 128, 16384 / 128), 256, smemG>>>(attnh, woutT, out, BATCH * SEQ, DIM, DIM);
}

// round 16
// speedup vs baseline: 1.1773x; 1.0291x over previous
#include <cuda_runtime.h>
#include <cuda_fp16.h>
#include <math.h>
#include <stdint.h>

#define BATCH 4
#define SEQ   4096
#define DIM   1024
#define HEADS 16
#define DH    64
#define CHUNK 128
#define NCHUNK 32
#define BH    (BATCH*HEADS)
#define FEAT_SCALE 0.35355339059327373f  // 64^-0.25

// ---------------- scratch (device globals; no allocation allowed) ----------------
__device__ __half g_xh   [BATCH*SEQ*DIM];     // fp16 x
__device__ __half g_wqkvT[3*DIM*DIM];         // K-major fp16
__device__ __half g_woutT[DIM*DIM];           // K-major fp16
__device__ __half g_qh  [BH*SEQ*DH];          // featurized q (fp16)
__device__ __half g_kh  [BH*SEQ*DH];          // featurized k (fp16)
__device__ __half g_vh  [BH*SEQ*DH];          // v (fp16)
__device__ __half g_attnh[BATCH*SEQ*DIM];     // attention out, fp16
__device__ float  g_kvch [BH*NCHUNK*DH*DH];   // per-chunk K^T V (fp32)
__device__ __half g_kvph [BH*NCHUNK*DH*DH];   // exclusive-prefix KVp (fp16)
__device__ float  g_ksch[BH*NCHUNK*DH];
__device__ float2 g_rope[SEQ*32];             // (cos*SCALE, sin*SCALE) per (n, d)

// ---------------- helpers ----------------
__device__ __forceinline__ uint32_t h2_to_u32(__half2 h) {
    __half2_raw r = *(__half2_raw*)&h;
    return (uint32_t)r.x | ((uint32_t)r.y << 16);
}
__device__ __forceinline__ __half2 u32_to_h2(uint32_t u) {
    __half2_raw r;
    r.x = (unsigned short)(u & 0xFFFF);
    r.y = (unsigned short)(u >> 16);
    return *(__half2*)&r;
}
__device__ __forceinline__ void cpasync16(void* dst, const void* src) {
    unsigned d = (unsigned)__cvta_generic_to_shared(dst);
    asm volatile("cp.async.ca.shared.global [%0], [%1], 16;" :: "r"(d), "l"(src));
}
#define CP_COMMIT()  asm volatile("cp.async.commit_group;")
#define CP_WAIT1()   asm volatile("cp.async.wait_group 1;")

#define MMA_F16(acc, a0, a1, a2, a3, b0, b1) \
    asm volatile("mma.sync.aligned.m16n8k16.row.col.f32.f16.f16.f32 " \
        "{%0,%1,%2,%3}, {%4,%5,%6,%7}, {%8,%9}, {%0,%1,%2,%3};" \
        : "+f"((acc)[0]), "+f"((acc)[1]), "+f"((acc)[2]), "+f"((acc)[3]) \
        : "r"(a0), "r"(a1), "r"(a2), "r"(a3), "r"(b0), "r"(b1))

#define LDMATRIX_X4(r0, r1, r2, r3, addr) \
    asm volatile("ldmatrix.sync.aligned.m8n8.x4.shared.b16 {%0,%1,%2,%3}, [%4];" \
        : "=r"(r0), "=r"(r1), "=r"(r2), "=r"(r3) : "r"(addr))

#define LDMATRIX_X4_TRANS(r0, r1, r2, r3, addr) \
    asm volatile("ldmatrix.sync.aligned.m8n8.x4.trans.shared.b16 {%0,%1,%2,%3}, [%4];" \
        : "=r"(r0), "=r"(r1), "=r"(r2), "=r"(r3) : "r"(addr))

__device__ __forceinline__ uint32_t smem_u32p(const void* p) {
    return (uint32_t)__cvta_generic_to_shared(p);
}
__device__ __forceinline__ float exp_fast(float y) {   // exp(y), |err| ~2ulp
    float r;
    asm("ex2.approx.f32 %0, %1;" : "=f"(r) : "f"(y * 1.4426950408889634f));
    return r;
}

// fp32 sincos, FMA Cody-Waite range reduction (accurate ~1e-7 for ang < 5000)
__device__ __forceinline__ void rope_sincos_f(float ang, float& s, float& c) {
    float qf = rintf(ang * 0.63661977f);
    float r = fmaf(-qf, 1.57079637e+0f, ang);
    r = fmaf(qf, 4.37113900e-8f, r);
    int qi = (int)qf & 3;
    float r2 = r * r;
    float sp = r * (1.0f + r2 * (-1.6666667e-1f + r2 * (8.3333337e-3f
              + r2 * (-1.9841270e-4f + r2 * 2.7557319e-6f))));
    float cp = 1.0f + r2 * (-0.5f + r2 * (4.1666668e-2f
              + r2 * (-1.3888889e-3f + r2 * 2.4801587e-5f)));
    switch (qi) {
        case 0:  s =  sp; c =  cp; break;
        case 1:  s =  cp; c = -sp; break;
        case 2:  s = -sp; c = -cp; break;
        default: s = -cp; c =  sp; break;
    }
}

// ---------------- prep: x->fp16 conversion + rope table (one launch) ----------------
#define N2X ((BATCH*SEQ*DIM)/2)
__global__ void prep_kernel(const float2* __restrict__ in, __half2* __restrict__ out,
                            float2* __restrict__ tbl) {
    int i = blockIdx.x * blockDim.x + threadIdx.x;
    if (i < N2X) {
        out[i] = __float22half2_rn(in[i]);
    } else {
        int idx = i - N2X;                     // SEQ*32 entries
        int d = idx & 31;
        int n = idx >> 5;
        float inv_f = (float)exp(-(double)d * (9.210340371976184 / 32.0));
        float ang = (float)n * inv_f;
        float s, c;
        rope_sincos_f(ang, s, c);
        tbl[idx] = make_float2(c * FEAT_SCALE, s * FEAT_SCALE);
    }
}

__global__ void transpose_f16(const float* __restrict__ W, __half* __restrict__ WT,
                              int K, int Nn) {
    __shared__ float t[32][33];
    int n0 = blockIdx.x * 32, k0 = blockIdx.y * 32;
    int tx = threadIdx.x, ty = threadIdx.y;
#pragma unroll
    for (int i = 0; i < 32; i += 8)
        t[ty + i][tx] = W[(size_t)(k0 + ty + i) * Nn + n0 + tx];
    __syncthreads();
#pragma unroll
    for (int i = 0; i < 32; i += 8)
        WT[(size_t)(n0 + ty + i) * K + k0 + tx] = __float2half(t[tx][ty + i]);
}

// ---------------- generic fp16 GEMM (128x128, single sync/iter) ----------------
#define STAGE_B 20480      // bytes per stage: A 10240 + B 10240 (pitch 80 B)
__global__ __launch_bounds__(256) void gemm_f16(
        const __half* __restrict__ A, const __half* __restrict__ BT,
        float* __restrict__ C, int M, int Nn, int K) {
    extern __shared__ char smc[];
    const int tid = threadIdx.x;
    const int bx = blockIdx.x, by = blockIdx.y;
    const int warp = tid >> 5, lane = tid & 31;
    const int gid = lane >> 2, tig = lane & 3;
    const int g = lane >> 3, rr = lane & 7;
    const int warpM = warp & 1, warpN = warp >> 1;
    const int mBase = warpM * 64;
    const int nBase = warpN * 32;

    const __half* Ab = A  + (size_t)(by * 128) * K;
    const __half* Bb = BT + (size_t)(bx * 128) * K;
    const uint32_t smbase = smem_u32p(smc);

    float acc[4][4][4];
#pragma unroll
    for (int mi = 0; mi < 4; mi++)
#pragma unroll
        for (int nj = 0; nj < 4; nj++)
#pragma unroll
            for (int r = 0; r < 4; r++) acc[mi][nj][r] = 0.0f;

    const int KT = K >> 5;

    auto load_tile = [&](int kt, char* buf) {
        char* As = buf;
        char* Bs = buf + 10240;
        int k0 = kt * 32;
#pragma unroll
        for (int i = 0; i < 2; i++) {
            int c = i * 256 + tid;
            int m = c >> 2, k8 = (c & 3) * 8;
            cpasync16(As + m * 80 + k8 * 2, Ab + (size_t)m * K + k0 + k8);
        }
#pragma unroll
        for (int i = 0; i < 2; i++) {
            int c = i * 256 + tid;
            int n = c >> 2, k8 = (c & 3) * 8;
            cpasync16(Bs + n * 80 + k8 * 2, Bb + (size_t)n * K + k0 + k8);
        }
    };

    load_tile(0, smc);
    CP_COMMIT();
    load_tile(1, smc + STAGE_B);
    CP_COMMIT();

    const uint32_t aRow = (uint32_t)((mBase + (g & 1) * 8 + rr) * 80) + (uint32_t)((g >> 1) * 16);
    const uint32_t bRow = (uint32_t)((nBase + (g >> 1) * 8 + rr) * 80) + (uint32_t)((g & 1) * 16);

    for (int kt = 0; kt < KT; kt++) {
        CP_WAIT1();
        __syncthreads();
        if (kt + 2 < KT) load_tile(kt + 2, smc + ((kt + 2) % 3) * STAGE_B);
        CP_COMMIT();

        uint32_t ab = smbase + (uint32_t)((kt % 3) * STAGE_B);
        uint32_t bb = ab + 10240;

#pragma unroll
        for (int s = 0; s < 2; s++) {
            uint32_t af[4][4];
            uint32_t bq[2][4];
            uint32_t aoff = ab + aRow + s * 32;
            uint32_t boff = bb + bRow + s * 32;
#pragma unroll
            for (int mi = 0; mi < 4; mi++)
                LDMATRIX_X4(af[mi][0], af[mi][1], af[mi][2], af[mi][3], aoff + mi * (16 * 80));
#pragma unroll
            for (int p = 0; p < 2; p++)
                LDMATRIX_X4(bq[p][0], bq[p][1], bq[p][2], bq[p][3], boff + p * (16 * 80));
#pragma unroll
            for (int mi = 0; mi < 4; mi++)
#pragma unroll
                for (int nj = 0; nj < 4; nj++)
                    MMA_F16(acc[mi][nj], af[mi][0], af[mi][1], af[mi][2], af[mi][3],
                            bq[nj >> 1][(nj & 1) * 2], bq[nj >> 1][(nj & 1) * 2 + 1]);
        }
    }

#pragma unroll
    for (int mi = 0; mi < 4; mi++) {
        int row = by * 128 + mBase + mi * 16 + gid;
#pragma unroll
        for (int nj = 0; nj < 4; nj++) {
            int col = bx * 128 + nBase + nj * 8 + tig * 2;
            *(float2*)(C + (size_t)row * Nn + col)       = make_float2(acc[mi][nj][0], acc[mi][nj][1]);
            *(float2*)(C + (size_t)(row + 8) * Nn + col) = make_float2(acc[mi][nj][2], acc[mi][nj][3]);
        }
    }
}

// ---------------- fused QKV GEMM + RoPE(table) + ELU featurize ----------------
__global__ __launch_bounds__(256) void gemm_qkv(
        const __half* __restrict__ A, const __half* __restrict__ BT,
        const float2* __restrict__ rope,
        __half* __restrict__ qh, __half* __restrict__ kh, __half* __restrict__ vh) {
    extern __shared__ char smc[];
    const int K = DIM;
    const int tid = threadIdx.x;
    const int bx = blockIdx.x, by = blockIdx.y;
    const int warp = tid >> 5, lane = tid & 31;
    const int gid = lane >> 2, tig = lane & 3;
    const int g = lane >> 3, rr = lane & 7;
    const int warpM = warp & 1, warpN = warp >> 1;
    const int mBase = warpM * 64;
    const int nBase = warpN * 32;

    const __half* Ab = A + (size_t)(by * 128) * K;
    const __half* Bb = BT + (size_t)(bx * 128) * K;
    const uint32_t smbase = smem_u32p(smc);

    float acc[4][4][4];
#pragma unroll
    for (int mi = 0; mi < 4; mi++)
#pragma unroll
        for (int nj = 0; nj < 4; nj++)
#pragma unroll
            for (int r = 0; r < 4; r++) acc[mi][nj][r] = 0.0f;

    const int KT = K >> 5;

    auto load_tile = [&](int kt, char* buf) {
        char* As = buf;
        char* Bs = buf + 10240;
        int k0 = kt * 32;
#pragma unroll
        for (int i = 0; i < 2; i++) {
            int c = i * 256 + tid;
            int m = c >> 2, k8 = (c & 3) * 8;
            cpasync16(As + m * 80 + k8 * 2, Ab + (size_t)m * K + k0 + k8);
        }
#pragma unroll
        for (int i = 0; i < 2; i++) {
            int c = i * 256 + tid;
            int n = c >> 2, k8 = (c & 3) * 8;
            cpasync16(Bs + n * 80 + k8 * 2, Bb + (size_t)n * K + k0 + k8);
        }
    };

    load_tile(0, smc);
    CP_COMMIT();
    load_tile(1, smc + STAGE_B);
    CP_COMMIT();

    const uint32_t aRow = (uint32_t)((mBase + (g & 1) * 8 + rr) * 80) + (uint32_t)((g >> 1) * 16);
    const uint32_t bRow = (uint32_t)((nBase + (g >> 1) * 8 + rr) * 80) + (uint32_t)((g & 1) * 16);

    for (int kt = 0; kt < KT; kt++) {
        CP_WAIT1();
        __syncthreads();
        if (kt + 2 < KT) load_tile(kt + 2, smc + ((kt + 2) % 3) * STAGE_B);
        CP_COMMIT();

        uint32_t ab = smbase + (uint32_t)((kt % 3) * STAGE_B);
        uint32_t bb = ab + 10240;

#pragma unroll
        for (int s = 0; s < 2; s++) {
            uint32_t af[4][4];
            uint32_t bq[2][4];
            uint32_t aoff = ab + aRow + s * 32;
            uint32_t boff = bb + bRow + s * 32;
#pragma unroll
            for (int mi = 0; mi < 4; mi++)
                LDMATRIX_X4(af[mi][0], af[mi][1], af[mi][2], af[mi][3], aoff + mi * (16 * 80));
#pragma unroll
            for (int p = 0; p < 2; p++)
                LDMATRIX_X4(bq[p][0], bq[p][1], bq[p][2], bq[p][3], boff + p * (16 * 80));
#pragma unroll
            for (int mi = 0; mi < 4; mi++)
#pragma unroll
                for (int nj = 0; nj < 4; nj++)
                    MMA_F16(acc[mi][nj], af[mi][0], af[mi][1], af[mi][2], af[mi][3],
                            bq[nj >> 1][(nj & 1) * 2], bq[nj >> 1][(nj & 1) * 2 + 1]);
        }
    }

    // ---- epilogue: stage tile fp32, featurize via table, store fp16 ----
    __syncthreads();
    float* St = (float*)smc;         // 128 x pitch 132 floats
#pragma unroll
    for (int mi = 0; mi < 4; mi++) {
        int r = mBase + mi * 16 + gid;
#pragma unroll
        for (int nj = 0; nj < 4; nj++) {
            int ccol = nBase + nj * 8 + tig * 2;
            *(float2*)&St[r * 132 + ccol]       = make_float2(acc[mi][nj][0], acc[mi][nj][1]);
            *(float2*)&St[(r + 8) * 132 + ccol] = make_float2(acc[mi][nj][2], acc[mi][nj][3]);
        }
    }
    __syncthreads();

    const int sel   = bx >> 3;           // 0=q, 1=k, 2=v
    const int hbase = (bx & 7) * 2;
    const int d     = tid & 31;
    const int hh    = (tid >> 5) & 1;
    const int rbase = tid >> 6;          // 0..3
    const int bb    = by >> 5;           // batch
    const int n0    = (by * 128) & 4095;

    __half* dst = (sel == 0) ? qh : ((sel == 1) ? kh : vh);

#pragma unroll 4
    for (int k = 0; k < 32; k++) {
        int row = rbase + k * 4;
        float x1 = St[row * 132 + hh * 64 + d];
        float x2 = St[row * 132 + hh * 64 + d + 32];
        float f1, f2;
        if (sel == 2) {
            f1 = x1; f2 = x2;
        } else {
            float2 cs = rope[(n0 + row) * 32 + d];     // (c*S, s*S)
            float y1 = x1 * cs.x - x2 * cs.y;
            float y2 = x1 * cs.y + x2 * cs.x;
            f1 = (y1 > 0.0f) ? y1 + 1.0f : exp_fast(y1);
            f2 = (y2 > 0.0f) ? y2 + 1.0f : exp_fast(y2);
        }
        size_t ob = (((size_t)(bb * HEADS + hbase + hh)) * SEQ + (n0 + row)) * DH + d;
        dst[ob]      = __float2half(f1);
        dst[ob + 32] = __float2half(f2);
    }
}

// ---------------- pass A: tensor-core per-chunk K^T V (64x64) and sum(k) ----------------
__global__ __launch_bounds__(256) void chunk_sums_tc(
        const __half* __restrict__ kh, const __half* __restrict__ vh,
        float* __restrict__ kvch, float* __restrict__ ksch) {
    extern __shared__ char smem[];
    __half* Kh = (__half*)smem;              // 128 x 144 B = 18432
    __half* Vh = (__half*)(smem + 18432);    // 18432
    float* red = (float*)(smem + 36864);     // [4][64] = 1024 B

    const int blk = blockIdx.x;
    const int c  = blk % NCHUNK;
    const int bh = blk / NCHUNK;
    const int tid = threadIdx.x;
    const int warp = tid >> 5, lane = tid & 31;
    const int gid = lane >> 2, tig = lane & 3;
    const int g = lane >> 3, rr = lane & 7;

    size_t gbase = (((size_t)bh) * SEQ + (size_t)c * CHUNK) * DH;
    for (int i = tid; i < 1024; i += 256) {
        int row = i >> 3, c16 = (i & 7) * 16;
        *(float4*)((char*)Kh + row * 144 + c16) = ((const float4*)(kh + gbase))[i];
        *(float4*)((char*)Vh + row * 144 + c16) = ((const float4*)(vh + gbase))[i];
    }
    __syncthreads();

    const uint32_t kbase = smem_u32p(Kh);
    const uint32_t vbase = smem_u32p(Vh);
    const int d0 = (warp & 3) * 16;
    const int m0 = (warp >> 2) * 32;

    float acc[4][4];
#pragma unroll
    for (int nt = 0; nt < 4; nt++)
#pragma unroll
        for (int r = 0; r < 4; r++) acc[nt][r] = 0.0f;

    const uint32_t aAddr = (uint32_t)(((g >> 1) * 8 + rr) * 144 + (d0 + (g & 1) * 8) * 2);
    const uint32_t bAddr = (uint32_t)(((g & 1) * 8 + rr) * 144 + (m0 + (g >> 1) * 8) * 2);

#pragma unroll
    for (int ks = 0; ks < 8; ks++) {
        uint32_t a0, a1, a2, a3;
        LDMATRIX_X4_TRANS(a0, a1, a2, a3, kbase + aAddr + (uint32_t)(ks * 16 * 144));
#pragma unroll
        for (int p = 0; p < 2; p++) {
            uint32_t b0, b1, b2, b3;
            LDMATRIX_X4_TRANS(b0, b1, b2, b3,
                              vbase + bAddr + (uint32_t)(ks * 16 * 144) + (uint32_t)(p * 32));
            MMA_F16(acc[p * 2],     a0, a1, a2, a3, b0, b1);
            MMA_F16(acc[p * 2 + 1], a0, a1, a2, a3, b2, b3);
        }
    }

    size_t obase = ((size_t)bh * NCHUNK + c) * (DH * DH);
    int row_lo = d0 + gid, row_hi = row_lo + 8;
#pragma unroll
    for (int nt = 0; nt < 4; nt++) {
        int col = m0 + nt * 8 + tig * 2;
        *(float2*)&kvch[obase + (size_t)row_lo * 64 + col] = make_float2(acc[nt][0], acc[nt][1]);
        *(float2*)&kvch[obase + (size_t)row_hi * 64 + col] = make_float2(acc[nt][2], acc[nt][3]);
    }

    // parallel ksum: 256 threads = 4 row-groups x 64 d
    {
        int d = tid & 63, part = tid >> 6;
        float ssum = 0.0f;
        int rbeg = part * 32;
#pragma unroll 8
        for (int r = rbeg; r < rbeg + 32; r++)
            ssum += __half2float(Kh[r * 72 + d]);
        red[part * 64 + d] = ssum;
    }
    __syncthreads();
    if (tid < 64) {
        float t = red[tid] + red[64 + tid] + red[128 + tid] + red[192 + tid];
        ksch[((size_t)bh * NCHUNK + c) * DH + tid] = t;
    }
}

// ---------------- pass B: exclusive prefix over chunks; KVp emitted fp16 ----------------
__global__ void prefix_kernel(const float* __restrict__ kvch, __half* __restrict__ kvph,
                              float* __restrict__ ksch) {
    int bh = blockIdx.x;
    for (int e = threadIdx.x; e < DH * DH; e += blockDim.x) {
        const float* p = &kvch[(size_t)bh * NCHUNK * (DH * DH) + e];
        __half* q = &kvph[(size_t)bh * NCHUNK * (DH * DH) + e];
        float r[NCHUNK];
#pragma unroll
        for (int c = 0; c < NCHUNK; c++) r[c] = p[(size_t)c * (DH * DH)];
        float acc = 0.0f;
#pragma unroll
        for (int c = 0; c < NCHUNK; c++) {
            q[(size_t)c * (DH * DH)] = __float2half(acc);
            acc += r[c];
        }
    }
    if (threadIdx.x < DH) {
        float* p = &ksch[(size_t)bh * NCHUNK * DH + threadIdx.x];
        float r[NCHUNK];
#pragma unroll
        for (int c = 0; c < NCHUNK; c++) r[c] = p[(size_t)c * DH];
        float acc = 0.0f;
#pragma unroll
        for (int c = 0; c < NCHUNK; c++) {
            float t = r[c];
            p[(size_t)c * DH] = acc;
            acc += t;
        }
    }
}

// ---------------- pass C: tensor-core per-chunk output (S kept in registers) ----------------
#define PQU 36
__global__ __launch_bounds__(256, 2) void chunk_out_tc(
        const __half* __restrict__ qh, const __half* __restrict__ kh,
        const __half* __restrict__ vh, const __half* __restrict__ kvph,
        const float* __restrict__ ksch, __half* __restrict__ attn) {
    extern __shared__ char smem[];
    __half* Qh   = (__half*)smem;                    // 128 x 144 B = 18432
    __half* Kh   = (__half*)(smem + 18432);          // 18432
    __half* Vh   = (__half*)(smem + 36864);          // 18432
    __half* KVph = (__half*)(smem + 55296);          // 64 x 144 B = 9216
    float* rowsum = (float*)(smem + 64512);          // 512
    float* den    = (float*)(smem + 65024);          // 512
    float* KSp    = (float*)(smem + 65536);          // 256  -> total 65792

    const int blk = blockIdx.x;
    const int c  = blk % NCHUNK;
    const int bh = blk / NCHUNK;
    const int b  = bh / HEADS;
    const int h  = bh % HEADS;
    const int tid = threadIdx.x;
    const int warp = tid >> 5, lane = tid & 31;
    const int gid = lane >> 2, tig = lane & 3;
    const int g = lane >> 3, rr = lane & 7;

    size_t gbase = (((size_t)bh) * SEQ + (size_t)c * CHUNK) * DH;
    for (int i = tid; i < 1024; i += 256) {
        int row = i >> 3, c16 = (i & 7) * 16;
        *(float4*)((char*)Qh + row * 144 + c16) = ((const float4*)(qh + gbase))[i];
        *(float4*)((char*)Kh + row * 144 + c16) = ((const float4*)(kh + gbase))[i];
        *(float4*)((char*)Vh + row * 144 + c16) = ((const float4*)(vh + gbase))[i];
    }
    {
        size_t kvbase = ((size_t)bh * NCHUNK + c) * (DH * DH);
        for (int i = tid; i < 512; i += 256) {
            int d = i >> 3, c16 = (i & 7) * 16;
            *(float4*)((char*)KVph + d * 144 + c16) = ((const float4*)(kvph + kvbase))[i];
        }
        if (tid < 64)
            KSp[tid] = ksch[((size_t)bh * NCHUNK + c) * DH + tid];
    }
    __syncthreads();

    const uint32_t* Qu = (const uint32_t*)Qh;
    const uint32_t qbase = smem_u32p(Qh);
    const uint32_t kbase = smem_u32p(Kh);
    const int r0 = warp * 16;

    const uint32_t aRowQ = (uint32_t)((r0 + (g & 1) * 8 + rr) * 144 + (g >> 1) * 16);
    const uint32_t bRowK = (uint32_t)(((g >> 1) * 8 + rr) * 144 + (g & 1) * 16);

    // ---- stage 1: S = Q K^T in registers; mask; rowsum; pack S to A-fragments ----
    uint32_t sA[8][4];     // per-warp S tile as fp16 A-fragments (k16 slice p)
    {
        float acc1[16][4];
#pragma unroll
        for (int nt = 0; nt < 16; nt++)
#pragma unroll
            for (int r = 0; r < 4; r++) acc1[nt][r] = 0.0f;

#pragma unroll
        for (int ks = 0; ks < 4; ks++) {
            uint32_t aq[4];
            LDMATRIX_X4(aq[0], aq[1], aq[2], aq[3], qbase + aRowQ + ks * 32);
#pragma unroll
            for (int p = 0; p < 8; p++) {
                uint32_t bk[4];
                LDMATRIX_X4(bk[0], bk[1], bk[2], bk[3],
                            kbase + bRowK + (uint32_t)(p * 16 * 144) + ks * 32);
                MMA_F16(acc1[2 * p],     aq[0], aq[1], aq[2], aq[3], bk[0], bk[1]);
                MMA_F16(acc1[2 * p + 1], aq[0], aq[1], aq[2], aq[3], bk[2], bk[3]);
            }
        }

        int row_lo = r0 + gid, row_hi = row_lo + 8;
        float sum_lo = 0.0f, sum_hi = 0.0f;
#pragma unroll
        for (int nt = 0; nt < 16; nt++) {
            int c0 = nt * 8 + tig * 2, c1 = c0 + 1;
            float v0 = (c0 <= row_lo) ? acc1[nt][0] : 0.0f;
            float v1 = (c1 <= row_lo) ? acc1[nt][1] : 0.0f;
            float v2 = (c0 <= row_hi) ? acc1[nt][2] : 0.0f;
            float v3 = (c1 <= row_hi) ? acc1[nt][3] : 0.0f;
            sum_lo += v0 + v1;
            sum_hi += v2 + v3;
            // C-fragment layout == A-fragment layout: pack masked S as fp16
            int p = nt >> 1, half = nt & 1;    // slice p, lower/upper 8 k-cols
            sA[p][half * 2]     = h2_to_u32(__floats2half2_rn(v0, v1));  // row lo
            sA[p][half * 2 + 1] = h2_to_u32(__floats2half2_rn(v2, v3));  // row hi
        }
        sum_lo += __shfl_xor_sync(0xffffffff, sum_lo, 1);
        sum_lo += __shfl_xor_sync(0xffffffff, sum_lo, 2);
        sum_hi += __shfl_xor_sync(0xffffffff, sum_hi, 1);
        sum_hi += __shfl_xor_sync(0xffffffff, sum_hi, 2);
        if (tig == 0) { rowsum[row_lo] = sum_lo; rowsum[row_hi] = sum_hi; }
    }
    __syncthreads();

    // ---- stage 2: denominators (fp32) ----
    if (tid < 128) {
        float dsum = rowsum[tid];
        const uint32_t* Qr = Qu + tid * PQU;
#pragma unroll
        for (int dd = 0; dd < 32; dd++) {
            float2 qv = __half22float2(u32_to_h2(Qr[dd]));
            dsum += qv.x * KSp[dd * 2] + qv.y * KSp[dd * 2 + 1];
        }
        den[tid] = 1.0f / fmaxf(dsum, 1e-6f);
    }
    __syncthreads();

    // ---- stage 3: O = S V + Q KVp  (S straight from registers) ----
    {
        float acc2[8][4];
#pragma unroll
        for (int nt = 0; nt < 8; nt++)
#pragma unroll
            for (int r = 0; r < 4; r++) acc2[nt][r] = 0.0f;

        const uint32_t vbase = smem_u32p(Vh);
        const uint32_t kvbase = smem_u32p(KVph);
        const int sel = lane >> 3;
        const int srow_in = ((sel & 1) << 3) + (lane & 7);
        const int ncol_in = (sel >> 1) << 3;

        // S @ V : contraction over s (128), A-fragments from sA
#pragma unroll
        for (int ks = 0; ks < 8; ks++) {
#pragma unroll
            for (int nt2 = 0; nt2 < 4; nt2++) {
                uint32_t addr = vbase + (uint32_t)((ks * 16 + srow_in) * 144 + (nt2 * 16 + ncol_in) * 2);
                uint32_t b0, b1, b2, b3;
                LDMATRIX_X4_TRANS(b0, b1, b2, b3, addr);
                MMA_F16(acc2[nt2 * 2],     sA[ks][0], sA[ks][1], sA[ks][2], sA[ks][3], b0, b1);
                MMA_F16(acc2[nt2 * 2 + 1], sA[ks][0], sA[ks][1], sA[ks][2], sA[ks][3], b2, b3);
            }
        }
        // Q @ KVp : contraction over d (64)
#pragma unroll
        for (int ks = 0; ks < 4; ks++) {
            uint32_t aq[4];
            LDMATRIX_X4(aq[0], aq[1], aq[2], aq[3], qbase + aRowQ + ks * 32);
#pragma unroll
            for (int nt2 = 0; nt2 < 4; nt2++) {
                uint32_t addr = kvbase + (uint32_t)((ks * 16 + srow_in) * 144 + (nt2 * 16 + ncol_in) * 2);
                uint32_t b0, b1, b2, b3;
                LDMATRIX_X4_TRANS(b0, b1, b2, b3, addr);
                MMA_F16(acc2[nt2 * 2],     aq[0], aq[1], aq[2], aq[3], b0, b1);
                MMA_F16(acc2[nt2 * 2 + 1], aq[0], aq[1], aq[2], aq[3], b2, b3);
            }
        }

        int row_lo = r0 + gid, row_hi = row_lo + 8;
        float inv_lo = den[row_lo], inv_hi = den[row_hi];
        size_t obL = ((size_t)b * SEQ + (size_t)c * CHUNK + row_lo) * DIM + h * 64;
        size_t obH = obL + (size_t)8 * DIM;
#pragma unroll
        for (int nt = 0; nt < 8; nt++) {
            int c0 = nt * 8 + tig * 2;
            *(__half2*)(attn + obL + c0) = __floats2half2_rn(acc2[nt][0] * inv_lo, acc2[nt][1] * inv_lo);
            *(__half2*)(attn + obH + c0) = __floats2half2_rn(acc2[nt][2] * inv_hi, acc2[nt][3] * inv_hi);
        }
    }
}

// ---------------- host launch ----------------
extern "C" void kernel_launch(void* const* d_in, const int* in_sizes, int n_in,
                              void* d_out, int out_size) {
    const float* x    = (const float*)d_in[0];
    const float* wqkv = (const float*)d_in[1];
    const float* wout = (const float*)d_in[2];
    float* out = (float*)d_out;

    float *kvch, *ksch;
    float2* rope;
    __half *xh, *wqkvT, *woutT, *qh, *kh, *vh, *attnh, *kvph;
    cudaGetSymbolAddress((void**)&xh,    g_xh);
    cudaGetSymbolAddress((void**)&wqkvT, g_wqkvT);
    cudaGetSymbolAddress((void**)&woutT, g_woutT);
    cudaGetSymbolAddress((void**)&qh,    g_qh);
    cudaGetSymbolAddress((void**)&kh,    g_kh);
    cudaGetSymbolAddress((void**)&vh,    g_vh);
    cudaGetSymbolAddress((void**)&attnh, g_attnh);
    cudaGetSymbolAddress((void**)&kvch,  g_kvch);
    cudaGetSymbolAddress((void**)&kvph,  g_kvph);
    cudaGetSymbolAddress((void**)&ksch,  g_ksch);
    cudaGetSymbolAddress((void**)&rope,  g_rope);

    const size_t smemG  = 3 * STAGE_B;               // 61440 B
    const size_t smemGQ = 128 * 132 * sizeof(float); // 67584 B (covers pipeline too)
    const size_t smemS  = 2 * 18432 + 1024;
    const size_t smemC  = 65792;
    cudaFuncSetAttribute(gemm_f16,      cudaFuncAttributeMaxDynamicSharedMemorySize, (int)smemG);
    cudaFuncSetAttribute(gemm_qkv,      cudaFuncAttributeMaxDynamicSharedMemorySize, (int)smemGQ);
    cudaFuncSetAttribute(chunk_sums_tc, cudaFuncAttributeMaxDynamicSharedMemorySize, (int)smemS);
    cudaFuncSetAttribute(chunk_out_tc,  cudaFuncAttributeMaxDynamicSharedMemorySize, (int)smemC);

    // 0) prep (x->fp16 + rope table in one launch) + weight transposes
    {
        int nblk = (N2X + SEQ * 32) / 256;
        prep_kernel<<<nblk, 256>>>((const float2*)x, (__half2*)xh, rope);
        transpose_f16<<<dim3(3 * DIM / 32, DIM / 32), dim3(32, 8)>>>(wqkv, wqkvT, DIM, 3 * DIM);
        transpose_f16<<<dim3(DIM / 32, DIM / 32), dim3(32, 8)>>>(wout, woutT, DIM, DIM);
    }

    // 1) fused qkv GEMM + RoPE(table) + ELU -> fp16 q/k/v in [bh][n][64]
    gemm_qkv<<<dim3(3072 / 128, 16384 / 128), 256, smemGQ>>>(xh, wqkvT, rope, qh, kh, vh);
    // 2) per-chunk K^T V sums (tensor cores, fp32 out)
    chunk_sums_tc<<<BH * NCHUNK, 256, smemS>>>(kh, vh, kvch, ksch);
    // 3) exclusive prefix across chunks -> fp16 KVp
    prefix_kernel<<<BH, 1024>>>(kvch, kvph, ksch);
    // 4) per-chunk outputs via tensor cores (S in registers, 2 CTAs/SM)
    chunk_out_tc<<<BH * NCHUNK, 256, smemC>>>(qh, kh, vh, kvph, ksch, attnh);
    // 5) final = attnh @ woutT^T
    gemm_f16<<<dim3(1024 / 128, 16384 / 128), 256, smemG>>>(attnh, woutT, out, BATCH * SEQ, DIM, DIM);
}